// round 3
// baseline (speedup 1.0000x reference)
#include <cuda_runtime.h>
#include <math.h>

#define BATCH 2
#define SEQ   4096
#define HID   1024
#define DIM   64
#define CHUNK 64
#define NCHUNK (SEQ/CHUNK)
#define NROWS (BATCH*SEQ)
#define GAMMA_F 0.96875f

// ---------------- scratch (static device globals; no runtime alloc) ----------
__device__ float g_Q[NROWS*DIM];
__device__ float g_K[NROWS*DIM];
__device__ float g_V[NROWS*DIM];
__device__ float g_G[BATCH*NCHUNK*DIM*DIM];  // per-chunk decayed K^T V
__device__ float g_A[BATCH*NCHUNK*DIM*DIM];  // scanned state before each chunk

// ============================ K1: fused QKV GEMM + xPos ======================
// C[8192 x 192] = X[8192 x 1024] @ [W_Q | W_K | W_V], xPos rotation+scale on
// Q (cols 0..63) and K (cols 64..127, downscale), V passthrough.
#define BM 64
#define BN 192
#define KT 16

__global__ __launch_bounds__(256)
void qkv_xpos_kernel(const float* __restrict__ X,
                     const float* __restrict__ WQ,
                     const float* __restrict__ WK,
                     const float* __restrict__ WV)
{
    __shared__ __align__(16) float Xs[BM][KT + 4];
    __shared__ __align__(16) float Ws[KT][BN];

    const int t    = threadIdx.x;
    const int r0   = blockIdx.x * BM;
    const int trow = t >> 5;   // 0..7   (8 row-groups of 8)
    const int tcol = t & 31;   // 0..31  (32 col-groups of 6)

    // X tile load mapping: 1 float4 per thread per k-tile
    const int xrow = t >> 2;
    const int xk   = (t & 3) << 2;
    const float* Xp = X + (size_t)(r0 + xrow) * HID + xk;

    // W tile load mapping: 3 float4 per thread per k-tile (fixed across kt)
    int wk_[3], wc_[3];
    const float* wp_[3];
    #pragma unroll
    for (int q = 0; q < 3; q++) {
        int f  = t * 12 + q * 4;
        int k  = f / BN;
        int c  = f - k * BN;
        wk_[q] = k;
        wc_[q] = c;
        int sel = c >> 6;
        int cl  = c & 63;
        const float* W = (sel == 0) ? WQ : ((sel == 1) ? WK : WV);
        wp_[q] = W + k * DIM + cl;
    }

    float acc[8][6];
    #pragma unroll
    for (int i = 0; i < 8; i++)
        #pragma unroll
        for (int j = 0; j < 6; j++) acc[i][j] = 0.f;

    for (int kt = 0; kt < HID; kt += KT) {
        // issue global loads before the barrier so latency overlaps compute
        float4 xv  = *(const float4*)(Xp + kt);
        float4 wv0 = *(const float4*)(wp_[0] + (size_t)kt * DIM);
        float4 wv1 = *(const float4*)(wp_[1] + (size_t)kt * DIM);
        float4 wv2 = *(const float4*)(wp_[2] + (size_t)kt * DIM);
        __syncthreads();
        *(float4*)&Xs[xrow][xk]        = xv;
        *(float4*)&Ws[wk_[0]][wc_[0]]  = wv0;
        *(float4*)&Ws[wk_[1]][wc_[1]]  = wv1;
        *(float4*)&Ws[wk_[2]][wc_[2]]  = wv2;
        __syncthreads();
        #pragma unroll
        for (int k = 0; k < KT; k++) {
            float a[8], b[6];
            #pragma unroll
            for (int i = 0; i < 8; i++) a[i] = Xs[trow * 8 + i][k];
            #pragma unroll
            for (int j = 0; j < 6; j++) b[j] = Ws[k][tcol * 6 + j];
            #pragma unroll
            for (int i = 0; i < 8; i++)
                #pragma unroll
                for (int j = 0; j < 6; j++)
                    acc[i][j] = fmaf(a[i], b[j], acc[i][j]);
        }
    }

    // ---------------- epilogue: xPos on Q/K, passthrough V ----------------
    #pragma unroll
    for (int i = 0; i < 8; i++) {
        int r    = r0 + trow * 8 + i;
        int pos  = r & (SEQ - 1);          // position within sequence
        float fp = (float)pos;
        #pragma unroll
        for (int p = 0; p < 3; p++) {
            int gc   = tcol * 6 + 2 * p;   // global col of the even element
            float v0 = acc[i][2 * p];
            float v1 = acc[i][2 * p + 1];
            if (gc >= 128) {               // V: passthrough
                int lc = gc - 128;
                g_V[r * DIM + lc]     = v0;
                g_V[r * DIM + lc + 1] = v1;
            } else {
                int  isK = (gc >= 64);
                int  lc  = gc & 63;
                int  pr  = lc >> 1;        // rotary pair index 0..31
                float inv_freq = 1.0f / powf(10000.0f, (float)pr * (1.0f / 32.0f));
                float sv = (2.0f * pr + 0.4f * 64.0f) * (1.0f / (1.4f * 64.0f));
                float sc = powf(sv, fp * (1.0f / 512.0f));
                if (isK) sc = 1.0f / sc;   // downscale for K
                float theta = fp * inv_freq;
                float sn, cs;
                sincosf(theta, &sn, &cs);
                cs *= sc;
                sn *= sc;
                float o0 = v0 * cs - v1 * sn;
                float o1 = v1 * cs + v0 * sn;
                float* dst = isK ? g_K : g_Q;
                dst[r * DIM + lc]     = o0;
                dst[r * DIM + lc + 1] = o1;
            }
        }
    }
}

// ============== K2: per-chunk decayed outer product G_c = sum_j g^(C-j) k v^T
__global__ __launch_bounds__(256)
void chunk_kv_kernel()
{
    __shared__ float Ks[CHUNK][DIM];
    __shared__ float Vs[CHUNK][DIM];
    __shared__ float w[CHUNK];
    const int t = threadIdx.x;
    const int b = blockIdx.x / NCHUNK;
    const int c = blockIdx.x - b * NCHUNK;
    const int base = (b * SEQ + c * CHUNK) * DIM;

    #pragma unroll
    for (int q = 0; q < 16; q++) {
        int f = t + 256 * q;
        ((float*)Ks)[f] = g_K[base + f];
        ((float*)Vs)[f] = g_V[base + f];
    }
    if (t < CHUNK) w[t] = powf(GAMMA_F, (float)(CHUNK - t));
    __syncthreads();

    const int a0 = (t >> 4) * 4;
    const int d0 = (t & 15) * 4;
    float acc[4][4];
    #pragma unroll
    for (int p = 0; p < 4; p++)
        #pragma unroll
        for (int q = 0; q < 4; q++) acc[p][q] = 0.f;

    for (int j = 0; j < CHUNK; j++) {
        float wj = w[j];
        float ka[4], vd[4];
        #pragma unroll
        for (int p = 0; p < 4; p++) ka[p] = Ks[j][a0 + p] * wj;
        #pragma unroll
        for (int q = 0; q < 4; q++) vd[q] = Vs[j][d0 + q];
        #pragma unroll
        for (int p = 0; p < 4; p++)
            #pragma unroll
            for (int q = 0; q < 4; q++)
                acc[p][q] = fmaf(ka[p], vd[q], acc[p][q]);
    }

    int gbase = (b * NCHUNK + c) * DIM * DIM;
    #pragma unroll
    for (int p = 0; p < 4; p++)
        #pragma unroll
        for (int q = 0; q < 4; q++)
            g_G[gbase + (a0 + p) * DIM + d0 + q] = acc[p][q];
}

// ================= K3: elementwise scan  A_{c+1} = g^64 A_c + G_c ===========
__global__ void scan_kernel()
{
    int e = blockIdx.x * blockDim.x + threadIdx.x;   // 0..8191
    if (e >= BATCH * DIM * DIM) return;
    int b  = e >> 12;
    int ed = e & (DIM * DIM - 1);
    const float g64 = powf(GAMMA_F, 64.0f);
    float acc = 0.f;
    int base = b * NCHUNK * DIM * DIM + ed;
    for (int c = 0; c < NCHUNK; c++) {
        g_A[base + c * DIM * DIM] = acc;             // state BEFORE chunk c
        acc = acc * g64 + g_G[base + c * DIM * DIM];
    }
}

// ====== K4: out_c = (Q K^T .* decay_mask) V  +  diag(g^i) (Q A_c) ===========
// 48KB static smem: Qs[64][64], KVs[64][64] XOR-swizzled, Ss[64][64]
#define SWZ(row, col) ((row) * 64 + ((col) ^ ((row) & 31)))

__global__ __launch_bounds__(256)
void out_kernel(float* __restrict__ out)
{
    __shared__ float Qs[DIM * DIM];
    __shared__ float KVs[DIM * DIM];
    __shared__ float Ss[DIM * DIM];

    const int t = threadIdx.x;
    const int b = blockIdx.x / NCHUNK;
    const int c = blockIdx.x - b * NCHUNK;
    const int base = (b * SEQ + c * CHUNK) * DIM;

    // load Q (plain) and K (swizzled)
    #pragma unroll
    for (int q = 0; q < 16; q++) {
        int f   = t + 256 * q;
        int row = f >> 6, col = f & 63;
        Qs[row * 64 + col] = g_Q[base + f];
        KVs[SWZ(row, col)] = g_K[base + f];
    }
    __syncthreads();

    const int ti = t >> 4, tj = t & 15;
    const int i0 = ti * 4, j0 = tj * 4;

    // ---- phase 1: S = (Q K^T) .* gamma^(i-j) mask
    float s[4][4];
    #pragma unroll
    for (int p = 0; p < 4; p++)
        #pragma unroll
        for (int q = 0; q < 4; q++) s[p][q] = 0.f;

    for (int a = 0; a < DIM; a++) {
        float qa[4], kb[4];
        #pragma unroll
        for (int p = 0; p < 4; p++) qa[p] = Qs[(i0 + p) * 64 + a];
        #pragma unroll
        for (int q = 0; q < 4; q++) kb[q] = KVs[SWZ(j0 + q, a)];
        #pragma unroll
        for (int p = 0; p < 4; p++)
            #pragma unroll
            for (int q = 0; q < 4; q++)
                s[p][q] = fmaf(qa[p], kb[q], s[p][q]);
    }
    #pragma unroll
    for (int p = 0; p < 4; p++) {
        int i = i0 + p;
        #pragma unroll
        for (int q = 0; q < 4; q++) {
            int j = j0 + q;
            float v = (i >= j) ? s[p][q] * powf(GAMMA_F, (float)(i - j)) : 0.f;
            Ss[i * 64 + j] = v;
        }
    }
    __syncthreads();   // S done; all K reads done

    // overwrite KVs with V (swizzled)
    #pragma unroll
    for (int q = 0; q < 16; q++) {
        int f   = t + 256 * q;
        int row = f >> 6, col = f & 63;
        KVs[SWZ(row, col)] = g_V[base + f];
    }
    __syncthreads();

    // ---- phase 2: out[i][d] = sum_j S[i][j] V[j][d] + g^i * sum_a Q[i][a] A[a][d]
    const int d0 = tj * 4;
    float o[4][4];
    #pragma unroll
    for (int p = 0; p < 4; p++)
        #pragma unroll
        for (int q = 0; q < 4; q++) o[p][q] = 0.f;

    for (int j = 0; j < CHUNK; j++) {
        float sp[4], vv[4];
        #pragma unroll
        for (int p = 0; p < 4; p++) sp[p] = Ss[(i0 + p) * 64 + j];
        #pragma unroll
        for (int q = 0; q < 4; q++) vv[q] = KVs[SWZ(j, d0 + q)];
        #pragma unroll
        for (int p = 0; p < 4; p++)
            #pragma unroll
            for (int q = 0; q < 4; q++)
                o[p][q] = fmaf(sp[p], vv[q], o[p][q]);
    }

    const float* A = g_A + (b * NCHUNK + c) * DIM * DIM;
    float oa[4][4];
    #pragma unroll
    for (int p = 0; p < 4; p++)
        #pragma unroll
        for (int q = 0; q < 4; q++) oa[p][q] = 0.f;

    for (int a = 0; a < DIM; a++) {
        float4 av = *(const float4*)(A + a * DIM + d0);
        #pragma unroll
        for (int p = 0; p < 4; p++) {
            float qa = Qs[(i0 + p) * 64 + a];
            oa[p][0] = fmaf(qa, av.x, oa[p][0]);
            oa[p][1] = fmaf(qa, av.y, oa[p][1]);
            oa[p][2] = fmaf(qa, av.z, oa[p][2]);
            oa[p][3] = fmaf(qa, av.w, oa[p][3]);
        }
    }

    #pragma unroll
    for (int p = 0; p < 4; p++) {
        float dec = powf(GAMMA_F, (float)(i0 + p));
        #pragma unroll
        for (int q = 0; q < 4; q++)
            out[base + (i0 + p) * DIM + d0 + q] = o[p][q] + dec * oa[p][q];
    }
}

// ============================== launch ======================================
extern "C" void kernel_launch(void* const* d_in, const int* in_sizes, int n_in,
                              void* d_out, int out_size)
{
    const float* X  = (const float*)d_in[0];
    const float* WQ = (const float*)d_in[1];
    const float* WK = (const float*)d_in[2];
    const float* WV = (const float*)d_in[3];
    float* out = (float*)d_out;

    qkv_xpos_kernel<<<NROWS / BM, 256>>>(X, WQ, WK, WV);
    chunk_kv_kernel<<<BATCH * NCHUNK, 256>>>();
    scan_kernel<<<(BATCH * DIM * DIM + 255) / 256, 256>>>();
    out_kernel<<<BATCH * NCHUNK, 256>>>(out);
}

// round 6
// speedup vs baseline: 1.6237x; 1.6237x over previous
#include <cuda_runtime.h>
#include <cuda_bf16.h>
#include <cstdint>
#include <math.h>

#define BATCH 2
#define SEQ   4096
#define HID   1024
#define DIM   64
#define CHUNK 64
#define NCHUNK (SEQ/CHUNK)
#define NROWS (BATCH*SEQ)
#define GAMMA_F 0.96875f
#define NTOT 192
#define LG2G (-0.045803689613124785f) // log2(0.96875)

// ---------------- scratch (static device globals; no runtime alloc) ----------
__device__ __nv_bfloat16 g_Wh[NTOT*HID];   // W transposed: [n][k], bf16 hi
__device__ __nv_bfloat16 g_Wl[NTOT*HID];   // bf16 lo residual
__device__ float2 g_qtab[32*SEQ];          // (cos*sc, sin*sc) [pr][pos]
__device__ float2 g_ktab[32*SEQ];          // (cos/sc, sin/sc)
__device__ float g_Q[NROWS*DIM];
__device__ float g_K[NROWS*DIM];
__device__ float g_V[NROWS*DIM];
__device__ float g_G[BATCH*NCHUNK*DIM*DIM];
__device__ float g_A[BATCH*NCHUNK*DIM*DIM];

// ---------------- warp-level bf16 MMA (sm_80+; works on plain sm_103) --------
__device__ __forceinline__ void mma_bf16(float* c, const uint32_t* a, const uint32_t* b) {
    asm volatile(
        "mma.sync.aligned.m16n8k16.row.col.f32.bf16.bf16.f32 "
        "{%0,%1,%2,%3}, {%4,%5,%6,%7}, {%8,%9}, {%0,%1,%2,%3};"
        : "+f"(c[0]), "+f"(c[1]), "+f"(c[2]), "+f"(c[3])
        : "r"(a[0]), "r"(a[1]), "r"(a[2]), "r"(a[3]), "r"(b[0]), "r"(b[1]));
}
__device__ __forceinline__ uint32_t pack_bf16(__nv_bfloat16 lo, __nv_bfloat16 hi) {
    return (uint32_t)__bfloat16_as_ushort(lo) | ((uint32_t)__bfloat16_as_ushort(hi) << 16);
}

// =========================== T0: xPos tables =================================
__global__ void tab_kernel() {
    int id  = blockIdx.x * blockDim.x + threadIdx.x;   // 0 .. 32*4096-1
    int pr  = id >> 12;
    int pos = id & (SEQ - 1);
    float fp = (float)pos;
    float inv_freq = 1.0f / powf(10000.0f, (float)pr * (1.0f / 32.0f));
    float sv = (2.0f * pr + 0.4f * 64.0f) * (1.0f / (1.4f * 64.0f));
    float sc = powf(sv, fp * (1.0f / 512.0f));
    float sn, cs;
    sincosf(fp * inv_freq, &sn, &cs);
    float2 q, k;
    q.x = cs * sc;  q.y = sn * sc;
    float rs = 1.0f / sc;
    k.x = cs * rs;  k.y = sn * rs;
    g_qtab[pr * SEQ + pos] = q;
    g_ktab[pr * SEQ + pos] = k;
}

// ============ T1: transpose W -> [n][k] bf16 hi/lo (192 x 1024) ==============
__global__ void convw_kernel(const float* __restrict__ WQ,
                             const float* __restrict__ WK,
                             const float* __restrict__ WV) {
    int n = blockIdx.x;                        // 0..191
    const float* W = (n < 64) ? WQ : ((n < 128) ? WK : WV);
    int cc = n & 63;
    for (int k = threadIdx.x; k < HID; k += blockDim.x) {
        float w = W[k * DIM + cc];
        __nv_bfloat16 h = __float2bfloat16(w);
        g_Wh[n * HID + k] = h;
        g_Wl[n * HID + k] = __float2bfloat16(w - __bfloat162float(h));
    }
}

// ======== K1: HMMA bf16 split GEMM + fused X conversion + xPos epilogue ======
// D[8192 x 192] = X @ [WQ|WK|WV]; per CTA M=64, N=192; warp tile 32x48.
#define PA 40   // smem pitch in bf16 units (80B): conflict-free frag loads

__global__ __launch_bounds__(256) void gemm_kernel(const float* __restrict__ X) {
    __shared__ __nv_bfloat16 Ah[64 * PA], Al[64 * PA];
    __shared__ __nv_bfloat16 Bh[NTOT * PA], Bl[NTOT * PA];

    const int t    = threadIdx.x;
    const int wid  = t >> 5, lane = t & 31;
    const int g    = lane >> 2, tig = lane & 3;
    const int wm   = wid >> 2, wn = wid & 3;     // warp grid 2 x 4
    const int r0   = blockIdx.x * 64;

    float C[2][6][4];
    #pragma unroll
    for (int mt = 0; mt < 2; mt++)
        #pragma unroll
        for (int nt = 0; nt < 6; nt++)
            #pragma unroll
            for (int i = 0; i < 4; i++) C[mt][nt][i] = 0.f;

    // prefetch registers
    float4 pxa[2];
    uint4  pbh[3], pbl[3];

    // ---- preload chunk 0
    #pragma unroll
    for (int j = 0; j < 2; j++) {
        int id = t + 256 * j;
        pxa[j] = *(const float4*)(X + (size_t)(r0 + (id >> 3)) * HID + (id & 7) * 4);
    }
    #pragma unroll
    for (int j = 0; j < 3; j++) {
        int id = t + 256 * j;
        int n = id >> 2, k8 = (id & 3) * 8;
        pbh[j] = *(const uint4*)(g_Wh + (size_t)n * HID + k8);
        pbl[j] = *(const uint4*)(g_Wl + (size_t)n * HID + k8);
    }

    for (int c = 0; c < 32; c++) {
        __syncthreads();           // previous chunk's compute done
        // ---- store A (fp32 -> bf16 hi/lo)
        #pragma unroll
        for (int j = 0; j < 2; j++) {
            int id = t + 256 * j;
            int row = id >> 3, col4 = (id & 7) * 4;
            float4 v = pxa[j];
            __nv_bfloat16 h0 = __float2bfloat16(v.x), h1 = __float2bfloat16(v.y);
            __nv_bfloat16 h2 = __float2bfloat16(v.z), h3 = __float2bfloat16(v.w);
            __nv_bfloat16 l0 = __float2bfloat16(v.x - __bfloat162float(h0));
            __nv_bfloat16 l1 = __float2bfloat16(v.y - __bfloat162float(h1));
            __nv_bfloat16 l2 = __float2bfloat16(v.z - __bfloat162float(h2));
            __nv_bfloat16 l3 = __float2bfloat16(v.w - __bfloat162float(h3));
            *(uint2*)(Ah + row * PA + col4) = make_uint2(pack_bf16(h0, h1), pack_bf16(h2, h3));
            *(uint2*)(Al + row * PA + col4) = make_uint2(pack_bf16(l0, l1), pack_bf16(l2, l3));
        }
        // ---- store B
        #pragma unroll
        for (int j = 0; j < 3; j++) {
            int id = t + 256 * j;
            int n = id >> 2, k8 = (id & 3) * 8;
            *(uint4*)(Bh + n * PA + k8) = pbh[j];
            *(uint4*)(Bl + n * PA + k8) = pbl[j];
        }
        __syncthreads();
        // ---- prefetch chunk c+1 (overlaps compute below)
        if (c < 31) {
            int kt = (c + 1) * 32;
            #pragma unroll
            for (int j = 0; j < 2; j++) {
                int id = t + 256 * j;
                pxa[j] = *(const float4*)(X + (size_t)(r0 + (id >> 3)) * HID + kt + (id & 7) * 4);
            }
            #pragma unroll
            for (int j = 0; j < 3; j++) {
                int id = t + 256 * j;
                int n = id >> 2, k8 = (id & 3) * 8;
                pbh[j] = *(const uint4*)(g_Wh + (size_t)n * HID + kt + k8);
                pbl[j] = *(const uint4*)(g_Wl + (size_t)n * HID + kt + k8);
            }
        }
        // ---- compute: 2 k16 steps
        #pragma unroll
        for (int ks = 0; ks < 2; ks++) {
            const int ko = ks * 16;
            uint32_t fah[2][4], fal[2][4];
            #pragma unroll
            for (int mt = 0; mt < 2; mt++) {
                const __nv_bfloat16* p = Ah + (wm * 32 + mt * 16 + g) * PA + ko + tig * 2;
                const __nv_bfloat16* q = Al + (wm * 32 + mt * 16 + g) * PA + ko + tig * 2;
                fah[mt][0] = *(const uint32_t*)p;
                fah[mt][1] = *(const uint32_t*)(p + 8 * PA);
                fah[mt][2] = *(const uint32_t*)(p + 8);
                fah[mt][3] = *(const uint32_t*)(p + 8 * PA + 8);
                fal[mt][0] = *(const uint32_t*)q;
                fal[mt][1] = *(const uint32_t*)(q + 8 * PA);
                fal[mt][2] = *(const uint32_t*)(q + 8);
                fal[mt][3] = *(const uint32_t*)(q + 8 * PA + 8);
            }
            uint32_t fbh[6][2], fbl[6][2];
            #pragma unroll
            for (int nt = 0; nt < 6; nt++) {
                const __nv_bfloat16* p = Bh + (wn * 48 + nt * 8 + g) * PA + ko + tig * 2;
                const __nv_bfloat16* q = Bl + (wn * 48 + nt * 8 + g) * PA + ko + tig * 2;
                fbh[nt][0] = *(const uint32_t*)p;
                fbh[nt][1] = *(const uint32_t*)(p + 8);
                fbl[nt][0] = *(const uint32_t*)q;
                fbl[nt][1] = *(const uint32_t*)(q + 8);
            }
            #pragma unroll
            for (int mt = 0; mt < 2; mt++)
                #pragma unroll
                for (int nt = 0; nt < 6; nt++) {
                    mma_bf16(C[mt][nt], fah[mt], fbh[nt]);
                    mma_bf16(C[mt][nt], fah[mt], fbl[nt]);
                    mma_bf16(C[mt][nt], fal[mt], fbh[nt]);
                }
        }
    }

    // ---------------- epilogue: xPos tables, write g_Q/g_K/g_V ---------------
    #pragma unroll
    for (int mt = 0; mt < 2; mt++) {
        int ra = r0 + wm * 32 + mt * 16 + g;
        int rb = ra + 8;
        int pa_ = ra & (SEQ - 1), pb_ = rb & (SEQ - 1);
        #pragma unroll
        for (int nt = 0; nt < 6; nt++) {
            int gc = wn * 48 + nt * 8 + tig * 2;
            float v0 = C[mt][nt][0], v1 = C[mt][nt][1];
            float v2 = C[mt][nt][2], v3 = C[mt][nt][3];
            if (gc >= 128) {               // V passthrough
                int lc = gc - 128;
                *(float2*)(g_V + (size_t)ra * DIM + lc) = make_float2(v0, v1);
                *(float2*)(g_V + (size_t)rb * DIM + lc) = make_float2(v2, v3);
            } else {                       // Q / K rotation
                const float2* tab = (gc < 64) ? g_qtab : g_ktab;
                int pr = (gc & 63) >> 1;
                float2 ta = tab[pr * SEQ + pa_];
                float2 tb = tab[pr * SEQ + pb_];
                float* dst = (gc < 64) ? g_Q : g_K;
                int lc = gc & 63;
                *(float2*)(dst + (size_t)ra * DIM + lc) =
                    make_float2(v0 * ta.x - v1 * ta.y, v1 * ta.x + v0 * ta.y);
                *(float2*)(dst + (size_t)rb * DIM + lc) =
                    make_float2(v2 * tb.x - v3 * tb.y, v3 * tb.x + v2 * tb.y);
            }
        }
    }
}

// ============== K2: per-chunk decayed outer product G_c = sum_j g^(C-j) k v^T
__global__ __launch_bounds__(256) void chunk_kv_kernel() {
    __shared__ float Ks[CHUNK][DIM];
    __shared__ float Vs[CHUNK][DIM];
    __shared__ float w[CHUNK];
    const int t = threadIdx.x;
    const int b = blockIdx.x / NCHUNK;
    const int c = blockIdx.x - b * NCHUNK;
    const int base = (b * SEQ + c * CHUNK) * DIM;

    #pragma unroll
    for (int q = 0; q < 16; q++) {
        int f = t + 256 * q;
        ((float*)Ks)[f] = g_K[base + f];
        ((float*)Vs)[f] = g_V[base + f];
    }
    if (t < CHUNK) w[t] = powf(GAMMA_F, (float)(CHUNK - t));
    __syncthreads();

    const int a0 = (t >> 4) * 4;
    const int d0 = (t & 15) * 4;
    float acc[4][4];
    #pragma unroll
    for (int p = 0; p < 4; p++)
        #pragma unroll
        for (int q = 0; q < 4; q++) acc[p][q] = 0.f;

    for (int j = 0; j < CHUNK; j++) {
        float wj = w[j];
        float ka[4], vd[4];
        #pragma unroll
        for (int p = 0; p < 4; p++) ka[p] = Ks[j][a0 + p] * wj;
        #pragma unroll
        for (int q = 0; q < 4; q++) vd[q] = Vs[j][d0 + q];
        #pragma unroll
        for (int p = 0; p < 4; p++)
            #pragma unroll
            for (int q = 0; q < 4; q++)
                acc[p][q] = fmaf(ka[p], vd[q], acc[p][q]);
    }

    int gbase = (b * NCHUNK + c) * DIM * DIM;
    #pragma unroll
    for (int p = 0; p < 4; p++)
        #pragma unroll
        for (int q = 0; q < 4; q++)
            g_G[gbase + (a0 + p) * DIM + d0 + q] = acc[p][q];
}

// ================= K3: elementwise scan  A_{c+1} = g^64 A_c + G_c ===========
__global__ void scan_kernel() {
    int e = blockIdx.x * blockDim.x + threadIdx.x;   // 0..8191
    if (e >= BATCH * DIM * DIM) return;
    int b  = e >> 12;
    int ed = e & (DIM * DIM - 1);
    const float g64 = powf(GAMMA_F, 64.0f);
    float acc = 0.f;
    int base = b * NCHUNK * DIM * DIM + ed;
    for (int c = 0; c < NCHUNK; c++) {
        g_A[base + c * DIM * DIM] = acc;
        acc = acc * g64 + g_G[base + c * DIM * DIM];
    }
}

// ====== K4: out = (Q K^T .* decay) V + diag(g^i)(Q A_c); 2 blocks/chunk =====
#define SWZ(row, col) ((row) * 64 + ((col) ^ ((row) & 31)))

__global__ __launch_bounds__(256) void out_kernel(float* __restrict__ out) {
    __shared__ float Qs[32 * 64];
    __shared__ float Ks[64 * 64];   // swizzled K, then reused for V
    __shared__ float Ss[32 * 64];

    const int t    = threadIdx.x;
    const int idx  = blockIdx.x;
    const int half = idx & 1;
    const int c    = (idx >> 1) & (NCHUNK - 1);
    const int b    = idx >> 7;
    const int base  = (b * SEQ + c * CHUNK) * DIM;
    const int rbase = base + half * 32 * DIM;

    #pragma unroll
    for (int q = 0; q < 8; q++) {
        int f = t + 256 * q;
        Qs[f] = g_Q[rbase + f];
    }
    #pragma unroll
    for (int q = 0; q < 16; q++) {
        int f = t + 256 * q;
        int row = f >> 6, col = f & 63;
        Ks[SWZ(row, col)] = g_K[base + f];
    }
    __syncthreads();

    const int ti = t >> 4, tj = t & 15;
    const int i0 = ti * 2, j0 = tj * 4;

    // ---- phase 1: S = (Q K^T) .* gamma^(gi-j) causal mask
    float s[2][4];
    #pragma unroll
    for (int p = 0; p < 2; p++)
        #pragma unroll
        for (int q = 0; q < 4; q++) s[p][q] = 0.f;

    for (int a = 0; a < DIM; a++) {
        float qa[2], kb[4];
        #pragma unroll
        for (int p = 0; p < 2; p++) qa[p] = Qs[(i0 + p) * 64 + a];
        #pragma unroll
        for (int q = 0; q < 4; q++) kb[q] = Ks[SWZ(j0 + q, a)];
        #pragma unroll
        for (int p = 0; p < 2; p++)
            #pragma unroll
            for (int q = 0; q < 4; q++)
                s[p][q] = fmaf(qa[p], kb[q], s[p][q]);
    }
    #pragma unroll
    for (int p = 0; p < 2; p++) {
        int gi = half * 32 + i0 + p;
        #pragma unroll
        for (int q = 0; q < 4; q++) {
            int j = j0 + q;
            float v = (gi >= j) ? s[p][q] * exp2f(LG2G * (float)(gi - j)) : 0.f;
            Ss[(i0 + p) * 64 + j] = v;
        }
    }
    __syncthreads();

    // overwrite Ks with V (swizzled)
    #pragma unroll
    for (int q = 0; q < 16; q++) {
        int f = t + 256 * q;
        int row = f >> 6, col = f & 63;
        Ks[SWZ(row, col)] = g_V[base + f];
    }
    __syncthreads();

    // ---- phase 2: out = S V + diag * (Q A)
    const int d0 = tj * 4;
    float o[2][4];
    #pragma unroll
    for (int p = 0; p < 2; p++)
        #pragma unroll
        for (int q = 0; q < 4; q++) o[p][q] = 0.f;

    for (int j = 0; j < CHUNK; j++) {
        float sp[2], vv[4];
        #pragma unroll
        for (int p = 0; p < 2; p++) sp[p] = Ss[(i0 + p) * 64 + j];
        #pragma unroll
        for (int q = 0; q < 4; q++) vv[q] = Ks[SWZ(j, d0 + q)];
        #pragma unroll
        for (int p = 0; p < 2; p++)
            #pragma unroll
            for (int q = 0; q < 4; q++)
                o[p][q] = fmaf(sp[p], vv[q], o[p][q]);
    }

    const float* A = g_A + (b * NCHUNK + c) * DIM * DIM;
    float oa[2][4];
    #pragma unroll
    for (int p = 0; p < 2; p++)
        #pragma unroll
        for (int q = 0; q < 4; q++) oa[p][q] = 0.f;

    for (int a = 0; a < DIM; a++) {
        float4 av = *(const float4*)(A + a * DIM + d0);
        #pragma unroll
        for (int p = 0; p < 2; p++) {
            float qa = Qs[(i0 + p) * 64 + a];
            oa[p][0] = fmaf(qa, av.x, oa[p][0]);
            oa[p][1] = fmaf(qa, av.y, oa[p][1]);
            oa[p][2] = fmaf(qa, av.z, oa[p][2]);
            oa[p][3] = fmaf(qa, av.w, oa[p][3]);
        }
    }

    #pragma unroll
    for (int p = 0; p < 2; p++) {
        int gi = half * 32 + i0 + p;
        float dec = exp2f(LG2G * (float)gi);
        float4 res;
        res.x = o[p][0] + dec * oa[p][0];
        res.y = o[p][1] + dec * oa[p][1];
        res.z = o[p][2] + dec * oa[p][2];
        res.w = o[p][3] + dec * oa[p][3];
        *(float4*)(out + rbase + (i0 + p) * 64 + d0) = res;
    }
}

// ============================== launch ======================================
extern "C" void kernel_launch(void* const* d_in, const int* in_sizes, int n_in,
                              void* d_out, int out_size)
{
    const float* X  = (const float*)d_in[0];
    const float* WQ = (const float*)d_in[1];
    const float* WK = (const float*)d_in[2];
    const float* WV = (const float*)d_in[3];
    float* out = (float*)d_out;

    tab_kernel<<<(32 * SEQ) / 256, 256>>>();
    convw_kernel<<<NTOT, 256>>>(WQ, WK, WV);
    gemm_kernel<<<NROWS / 64, 256>>>(X);
    chunk_kv_kernel<<<BATCH * NCHUNK, 256>>>();
    scan_kernel<<<(BATCH * DIM * DIM + 255) / 256, 256>>>();
    out_kernel<<<BATCH * NCHUNK * 2, 256>>>(out);
}

// round 7
// speedup vs baseline: 1.7630x; 1.0858x over previous
#include <cuda_runtime.h>
#include <cuda_bf16.h>
#include <cstdint>
#include <math.h>

#define BATCH 2
#define SEQ   4096
#define HID   1024
#define DIM   64
#define CHUNK 64
#define NCHUNK (SEQ/CHUNK)
#define NROWS (BATCH*SEQ)
#define GAMMA_F 0.96875f
#define NTOT 192
#define LG2G (-0.045803689613124785f) // log2(0.96875)

// ---------------- scratch (static device globals; no runtime alloc) ----------
__device__ __nv_bfloat16 g_Wh[NTOT*HID];   // W transposed: [n][k], bf16 hi
__device__ __nv_bfloat16 g_Wl[NTOT*HID];   // bf16 lo residual
__device__ float2 g_qtab[32*SEQ];          // (cos*sc, sin*sc) [pr][pos]
__device__ float2 g_ktab[32*SEQ];          // (cos/sc, sin/sc)
__device__ float g_Q[NROWS*DIM];
__device__ float g_K[NROWS*DIM];
__device__ float g_V[NROWS*DIM];
__device__ float g_G[BATCH*NCHUNK*DIM*DIM];
__device__ float g_A[BATCH*NCHUNK*DIM*DIM];

// ---------------- warp-level bf16 MMA + ldmatrix (sm_75+/80+) ----------------
__device__ __forceinline__ void mma_bf16(float* c, const uint32_t* a, const uint32_t* b) {
    asm volatile(
        "mma.sync.aligned.m16n8k16.row.col.f32.bf16.bf16.f32 "
        "{%0,%1,%2,%3}, {%4,%5,%6,%7}, {%8,%9}, {%0,%1,%2,%3};"
        : "+f"(c[0]), "+f"(c[1]), "+f"(c[2]), "+f"(c[3])
        : "r"(a[0]), "r"(a[1]), "r"(a[2]), "r"(a[3]), "r"(b[0]), "r"(b[1]));
}
__device__ __forceinline__ void ldsm_x4(uint32_t* r, uint32_t addr) {
    asm volatile("ldmatrix.sync.aligned.m8n8.x4.shared.b16 {%0,%1,%2,%3}, [%4];"
        : "=r"(r[0]), "=r"(r[1]), "=r"(r[2]), "=r"(r[3]) : "r"(addr));
}
__device__ __forceinline__ uint32_t pack_bf16(__nv_bfloat16 lo, __nv_bfloat16 hi) {
    return (uint32_t)__bfloat16_as_ushort(lo) | ((uint32_t)__bfloat16_as_ushort(hi) << 16);
}

// ================= P0: merged prep (xPos tables + W transpose/split) =========
__global__ void prep_kernel(const float* __restrict__ WQ,
                            const float* __restrict__ WK,
                            const float* __restrict__ WV) {
    int bid = blockIdx.x;
    int t   = threadIdx.x;
    if (bid < 512) {
        int id  = bid * 256 + t;            // 0 .. 32*4096-1
        int pr  = id >> 12;
        int pos = id & (SEQ - 1);
        float fp = (float)pos;
        float inv_freq = 1.0f / powf(10000.0f, (float)pr * (1.0f / 32.0f));
        float sv = (2.0f * pr + 0.4f * 64.0f) * (1.0f / (1.4f * 64.0f));
        float sc = powf(sv, fp * (1.0f / 512.0f));
        float sn, cs;
        sincosf(fp * inv_freq, &sn, &cs);
        float2 q, k;
        q.x = cs * sc;  q.y = sn * sc;
        float rs = 1.0f / sc;
        k.x = cs * rs;  k.y = sn * rs;
        g_qtab[pr * SEQ + pos] = q;
        g_ktab[pr * SEQ + pos] = k;
    } else {
        int n = bid - 512;                  // 0..191
        const float* W = (n < 64) ? WQ : ((n < 128) ? WK : WV);
        int cc = n & 63;
        for (int k = t; k < HID; k += 256) {
            float w = W[k * DIM + cc];
            __nv_bfloat16 h = __float2bfloat16(w);
            g_Wh[n * HID + k] = h;
            g_Wl[n * HID + k] = __float2bfloat16(w - __bfloat162float(h));
        }
    }
}

// ======== K1: HMMA bf16 split GEMM (ldmatrix frags) + xPos epilogue ==========
// D[8192 x 192] = X @ [WQ|WK|WV]; per CTA M=64, N=192; warp tile 32x48.
#define PA 40   // smem pitch in bf16 units (80B): 20-bank stride, LDSM conflict-free

__global__ __launch_bounds__(256) void gemm_kernel(const float* __restrict__ X) {
    __shared__ __nv_bfloat16 Ah[64 * PA], Al[64 * PA];
    __shared__ __nv_bfloat16 Bh[NTOT * PA], Bl[NTOT * PA];

    const int t    = threadIdx.x;
    const int wid  = t >> 5, lane = t & 31;
    const int g    = lane >> 2, tig = lane & 3;
    const int wm   = wid >> 2, wn = wid & 3;     // warp grid 2 x 4
    const int r0   = blockIdx.x * 64;

    // smem uint32 bases for ldmatrix
    const uint32_t uAh = (uint32_t)__cvta_generic_to_shared(Ah);
    const uint32_t uAl = (uint32_t)__cvta_generic_to_shared(Al);
    const uint32_t uBh = (uint32_t)__cvta_generic_to_shared(Bh);
    const uint32_t uBl = (uint32_t)__cvta_generic_to_shared(Bl);
    // per-lane ldmatrix element offsets (in bf16 units)
    const int aoff = (wm * 32 + (lane & 15)) * PA + ((lane >> 4) << 3);
    const int boff = (wn * 48 + ((lane >> 4) << 3) + (lane & 7)) * PA + (((lane >> 3) & 1) << 3);

    float C[2][6][4];
    #pragma unroll
    for (int mt = 0; mt < 2; mt++)
        #pragma unroll
        for (int nt = 0; nt < 6; nt++)
            #pragma unroll
            for (int i = 0; i < 4; i++) C[mt][nt][i] = 0.f;

    // prefetch registers
    float4 pxa[2];
    uint4  pbh[3], pbl[3];

    #pragma unroll
    for (int j = 0; j < 2; j++) {
        int id = t + 256 * j;
        pxa[j] = *(const float4*)(X + (size_t)(r0 + (id >> 3)) * HID + (id & 7) * 4);
    }
    #pragma unroll
    for (int j = 0; j < 3; j++) {
        int id = t + 256 * j;
        int n = id >> 2, k8 = (id & 3) * 8;
        pbh[j] = *(const uint4*)(g_Wh + (size_t)n * HID + k8);
        pbl[j] = *(const uint4*)(g_Wl + (size_t)n * HID + k8);
    }

    for (int c = 0; c < 32; c++) {
        __syncthreads();           // previous chunk's compute done
        // ---- store A (fp32 -> bf16 hi/lo)
        #pragma unroll
        for (int j = 0; j < 2; j++) {
            int id = t + 256 * j;
            int row = id >> 3, col4 = (id & 7) * 4;
            float4 v = pxa[j];
            __nv_bfloat16 h0 = __float2bfloat16(v.x), h1 = __float2bfloat16(v.y);
            __nv_bfloat16 h2 = __float2bfloat16(v.z), h3 = __float2bfloat16(v.w);
            __nv_bfloat16 l0 = __float2bfloat16(v.x - __bfloat162float(h0));
            __nv_bfloat16 l1 = __float2bfloat16(v.y - __bfloat162float(h1));
            __nv_bfloat16 l2 = __float2bfloat16(v.z - __bfloat162float(h2));
            __nv_bfloat16 l3 = __float2bfloat16(v.w - __bfloat162float(h3));
            *(uint2*)(Ah + row * PA + col4) = make_uint2(pack_bf16(h0, h1), pack_bf16(h2, h3));
            *(uint2*)(Al + row * PA + col4) = make_uint2(pack_bf16(l0, l1), pack_bf16(l2, l3));
        }
        #pragma unroll
        for (int j = 0; j < 3; j++) {
            int id = t + 256 * j;
            int n = id >> 2, k8 = (id & 3) * 8;
            *(uint4*)(Bh + n * PA + k8) = pbh[j];
            *(uint4*)(Bl + n * PA + k8) = pbl[j];
        }
        __syncthreads();
        // ---- prefetch chunk c+1 (overlaps compute below)
        if (c < 31) {
            int kt = (c + 1) * 32;
            #pragma unroll
            for (int j = 0; j < 2; j++) {
                int id = t + 256 * j;
                pxa[j] = *(const float4*)(X + (size_t)(r0 + (id >> 3)) * HID + kt + (id & 7) * 4);
            }
            #pragma unroll
            for (int j = 0; j < 3; j++) {
                int id = t + 256 * j;
                int n = id >> 2, k8 = (id & 3) * 8;
                pbh[j] = *(const uint4*)(g_Wh + (size_t)n * HID + kt + k8);
                pbl[j] = *(const uint4*)(g_Wl + (size_t)n * HID + kt + k8);
            }
        }
        // ---- compute: 2 k16 steps, fragments via ldmatrix
        #pragma unroll
        for (int ks = 0; ks < 2; ks++) {
            const int ko = ks * 16;
            uint32_t fah[2][4], fal[2][4];
            #pragma unroll
            for (int mt = 0; mt < 2; mt++) {
                uint32_t eo = (uint32_t)(aoff + mt * 16 * PA + ko) * 2;
                ldsm_x4(fah[mt], uAh + eo);
                ldsm_x4(fal[mt], uAl + eo);
            }
            uint32_t fbh[6][2], fbl[6][2];
            #pragma unroll
            for (int p3 = 0; p3 < 3; p3++) {
                uint32_t eo = (uint32_t)(boff + p3 * 16 * PA + ko) * 2;
                uint32_t tmp[4];
                ldsm_x4(tmp, uBh + eo);
                fbh[2*p3][0] = tmp[0]; fbh[2*p3][1] = tmp[1];
                fbh[2*p3+1][0] = tmp[2]; fbh[2*p3+1][1] = tmp[3];
                ldsm_x4(tmp, uBl + eo);
                fbl[2*p3][0] = tmp[0]; fbl[2*p3][1] = tmp[1];
                fbl[2*p3+1][0] = tmp[2]; fbl[2*p3+1][1] = tmp[3];
            }
            #pragma unroll
            for (int mt = 0; mt < 2; mt++)
                #pragma unroll
                for (int nt = 0; nt < 6; nt++) {
                    mma_bf16(C[mt][nt], fah[mt], fbh[nt]);
                    mma_bf16(C[mt][nt], fah[mt], fbl[nt]);
                    mma_bf16(C[mt][nt], fal[mt], fbh[nt]);
                }
        }
    }

    // ---------------- epilogue: xPos tables, write g_Q/g_K/g_V ---------------
    #pragma unroll
    for (int mt = 0; mt < 2; mt++) {
        int ra = r0 + wm * 32 + mt * 16 + g;
        int rb = ra + 8;
        int pa_ = ra & (SEQ - 1), pb_ = rb & (SEQ - 1);
        #pragma unroll
        for (int nt = 0; nt < 6; nt++) {
            int gc = wn * 48 + nt * 8 + tig * 2;
            float v0 = C[mt][nt][0], v1 = C[mt][nt][1];
            float v2 = C[mt][nt][2], v3 = C[mt][nt][3];
            if (gc >= 128) {               // V passthrough
                int lc = gc - 128;
                *(float2*)(g_V + (size_t)ra * DIM + lc) = make_float2(v0, v1);
                *(float2*)(g_V + (size_t)rb * DIM + lc) = make_float2(v2, v3);
            } else {                       // Q / K rotation
                const float2* tab = (gc < 64) ? g_qtab : g_ktab;
                int pr = (gc & 63) >> 1;
                float2 ta = tab[pr * SEQ + pa_];
                float2 tb = tab[pr * SEQ + pb_];
                float* dst = (gc < 64) ? g_Q : g_K;
                int lc = gc & 63;
                *(float2*)(dst + (size_t)ra * DIM + lc) =
                    make_float2(v0 * ta.x - v1 * ta.y, v1 * ta.x + v0 * ta.y);
                *(float2*)(dst + (size_t)rb * DIM + lc) =
                    make_float2(v2 * tb.x - v3 * tb.y, v3 * tb.x + v2 * tb.y);
            }
        }
    }
}

// ====== K2: per-chunk decayed outer product, 2 blocks per chunk (d-split) ====
__global__ __launch_bounds__(256) void chunk_kv_kernel() {
    __shared__ float Ks[CHUNK][DIM];
    __shared__ float Vs[CHUNK][32];
    __shared__ float w[CHUNK];
    const int t   = threadIdx.x;
    const int idx = blockIdx.x;
    const int dh  = idx & 1;
    const int c   = (idx >> 1) & (NCHUNK - 1);
    const int b   = idx >> 7;
    const int base = (b * SEQ + c * CHUNK) * DIM;

    #pragma unroll
    for (int q = 0; q < 16; q++) {
        int f = t + 256 * q;
        ((float*)Ks)[f] = g_K[base + f];
    }
    #pragma unroll
    for (int q = 0; q < 8; q++) {
        int f = t + 256 * q;              // 0..2047 -> row f>>5, col f&31
        Vs[f >> 5][f & 31] = g_V[base + (f >> 5) * DIM + dh * 32 + (f & 31)];
    }
    if (t < CHUNK) w[t] = powf(GAMMA_F, (float)(CHUNK - t));
    __syncthreads();

    const int a0 = (t >> 4) * 4;
    const int dl = (t & 15) * 2;
    float acc[4][2];
    #pragma unroll
    for (int p = 0; p < 4; p++) { acc[p][0] = 0.f; acc[p][1] = 0.f; }

    for (int j = 0; j < CHUNK; j++) {
        float wj = w[j];
        float ka[4], v0 = Vs[j][dl], v1 = Vs[j][dl + 1];
        #pragma unroll
        for (int p = 0; p < 4; p++) ka[p] = Ks[j][a0 + p] * wj;
        #pragma unroll
        for (int p = 0; p < 4; p++) {
            acc[p][0] = fmaf(ka[p], v0, acc[p][0]);
            acc[p][1] = fmaf(ka[p], v1, acc[p][1]);
        }
    }

    int gbase = (b * NCHUNK + c) * DIM * DIM;
    #pragma unroll
    for (int p = 0; p < 4; p++)
        *(float2*)(g_G + gbase + (a0 + p) * DIM + dh * 32 + dl) =
            make_float2(acc[p][0], acc[p][1]);
}

// ================= K3: elementwise scan  A_{c+1} = g^64 A_c + G_c ===========
__global__ void scan_kernel() {
    int e = blockIdx.x * blockDim.x + threadIdx.x;   // 0..8191
    if (e >= BATCH * DIM * DIM) return;
    int b  = e >> 12;
    int ed = e & (DIM * DIM - 1);
    const float g64 = powf(GAMMA_F, 64.0f);
    float acc = 0.f;
    int base = b * NCHUNK * DIM * DIM + ed;
    for (int c = 0; c < NCHUNK; c++) {
        g_A[base + c * DIM * DIM] = acc;
        acc = acc * g64 + g_G[base + c * DIM * DIM];
    }
}

// ====== K4: out = (Q K^T .* decay) V + diag(g^i)(Q A_c); 2 blocks/chunk =====
#define SWZ(row, col) ((row) * 64 + ((col) ^ ((row) & 31)))

__global__ __launch_bounds__(256) void out_kernel(float* __restrict__ out) {
    __shared__ float Qs[32 * 64];
    __shared__ float Ks[64 * 64];   // swizzled K, then reused for V
    __shared__ float Ss[32 * 64];

    const int t    = threadIdx.x;
    const int idx  = blockIdx.x;
    const int half = idx & 1;
    const int c    = (idx >> 1) & (NCHUNK - 1);
    const int b    = idx >> 7;
    const int base  = (b * SEQ + c * CHUNK) * DIM;
    const int rbase = base + half * 32 * DIM;

    #pragma unroll
    for (int q = 0; q < 8; q++) {
        int f = t + 256 * q;
        Qs[f] = g_Q[rbase + f];
    }
    #pragma unroll
    for (int q = 0; q < 16; q++) {
        int f = t + 256 * q;
        int row = f >> 6, col = f & 63;
        Ks[SWZ(row, col)] = g_K[base + f];
    }
    __syncthreads();

    const int ti = t >> 4, tj = t & 15;
    const int i0 = ti * 2, j0 = tj * 4;

    // ---- phase 1: S = (Q K^T) .* gamma^(gi-j) causal mask
    float s[2][4];
    #pragma unroll
    for (int p = 0; p < 2; p++)
        #pragma unroll
        for (int q = 0; q < 4; q++) s[p][q] = 0.f;

    for (int a = 0; a < DIM; a++) {
        float qa[2], kb[4];
        #pragma unroll
        for (int p = 0; p < 2; p++) qa[p] = Qs[(i0 + p) * 64 + a];
        #pragma unroll
        for (int q = 0; q < 4; q++) kb[q] = Ks[SWZ(j0 + q, a)];
        #pragma unroll
        for (int p = 0; p < 2; p++)
            #pragma unroll
            for (int q = 0; q < 4; q++)
                s[p][q] = fmaf(qa[p], kb[q], s[p][q]);
    }
    #pragma unroll
    for (int p = 0; p < 2; p++) {
        int gi = half * 32 + i0 + p;
        #pragma unroll
        for (int q = 0; q < 4; q++) {
            int j = j0 + q;
            float v = (gi >= j) ? s[p][q] * exp2f(LG2G * (float)(gi - j)) : 0.f;
            Ss[(i0 + p) * 64 + j] = v;
        }
    }
    __syncthreads();

    // overwrite Ks with V (swizzled)
    #pragma unroll
    for (int q = 0; q < 16; q++) {
        int f = t + 256 * q;
        int row = f >> 6, col = f & 63;
        Ks[SWZ(row, col)] = g_V[base + f];
    }
    __syncthreads();

    // ---- phase 2: out = S V + diag * (Q A)
    const int d0 = tj * 4;
    float o[2][4];
    #pragma unroll
    for (int p = 0; p < 2; p++)
        #pragma unroll
        for (int q = 0; q < 4; q++) o[p][q] = 0.f;

    for (int j = 0; j < CHUNK; j++) {
        float sp[2], vv[4];
        #pragma unroll
        for (int p = 0; p < 2; p++) sp[p] = Ss[(i0 + p) * 64 + j];
        #pragma unroll
        for (int q = 0; q < 4; q++) vv[q] = Ks[SWZ(j, d0 + q)];
        #pragma unroll
        for (int p = 0; p < 2; p++)
            #pragma unroll
            for (int q = 0; q < 4; q++)
                o[p][q] = fmaf(sp[p], vv[q], o[p][q]);
    }

    const float* A = g_A + (b * NCHUNK + c) * DIM * DIM;
    float oa[2][4];
    #pragma unroll
    for (int p = 0; p < 2; p++)
        #pragma unroll
        for (int q = 0; q < 4; q++) oa[p][q] = 0.f;

    for (int a = 0; a < DIM; a++) {
        float4 av = *(const float4*)(A + a * DIM + d0);
        #pragma unroll
        for (int p = 0; p < 2; p++) {
            float qa = Qs[(i0 + p) * 64 + a];
            oa[p][0] = fmaf(qa, av.x, oa[p][0]);
            oa[p][1] = fmaf(qa, av.y, oa[p][1]);
            oa[p][2] = fmaf(qa, av.z, oa[p][2]);
            oa[p][3] = fmaf(qa, av.w, oa[p][3]);
        }
    }

    #pragma unroll
    for (int p = 0; p < 2; p++) {
        int gi = half * 32 + i0 + p;
        float dec = exp2f(LG2G * (float)gi);
        float4 res;
        res.x = o[p][0] + dec * oa[p][0];
        res.y = o[p][1] + dec * oa[p][1];
        res.z = o[p][2] + dec * oa[p][2];
        res.w = o[p][3] + dec * oa[p][3];
        *(float4*)(out + rbase + (i0 + p) * 64 + d0) = res;
    }
}

// ============================== launch ======================================
extern "C" void kernel_launch(void* const* d_in, const int* in_sizes, int n_in,
                              void* d_out, int out_size)
{
    const float* X  = (const float*)d_in[0];
    const float* WQ = (const float*)d_in[1];
    const float* WK = (const float*)d_in[2];
    const float* WV = (const float*)d_in[3];
    float* out = (float*)d_out;

    prep_kernel<<<512 + NTOT, 256>>>(WQ, WK, WV);
    gemm_kernel<<<NROWS / 64, 256>>>(X);
    chunk_kv_kernel<<<BATCH * NCHUNK * 2, 256>>>();
    scan_kernel<<<(BATCH * DIM * DIM + 255) / 256, 256>>>();
    out_kernel<<<BATCH * NCHUNK * 2, 256>>>(out);
}

// round 8
// speedup vs baseline: 1.9922x; 1.1300x over previous
#include <cuda_runtime.h>
#include <cuda_bf16.h>
#include <cstdint>
#include <math.h>

#define BATCH 2
#define SEQ   4096
#define HID   1024
#define DIM   64
#define CHUNK 64
#define NCHUNK (SEQ/CHUNK)
#define NROWS (BATCH*SEQ)
#define GAMMA_F 0.96875f
#define NTOT 192
#define LG2G (-0.045803689613124785f) // log2(0.96875)

// ---------------- scratch (static device globals; no runtime alloc) ----------
__device__ __nv_bfloat16 g_Wh[NTOT*HID];   // W transposed: [n][k], bf16 hi
__device__ __nv_bfloat16 g_Wl[NTOT*HID];   // bf16 lo residual
__device__ float2 g_qtab[32*SEQ];          // (cos*sc, sin*sc) [pr][pos]
__device__ float2 g_ktab[32*SEQ];          // (cos/sc, sin/sc)
__device__ float g_Q[NROWS*DIM];
__device__ float g_K[NROWS*DIM];
__device__ float g_V[NROWS*DIM];
__device__ float g_G[BATCH*NCHUNK*DIM*DIM];
__device__ float g_A[BATCH*NCHUNK*DIM*DIM];

// ---------------- warp-level bf16 MMA + ldmatrix (sm_75+/80+) ----------------
__device__ __forceinline__ void mma_bf16(float* c, const uint32_t* a, const uint32_t* b) {
    asm volatile(
        "mma.sync.aligned.m16n8k16.row.col.f32.bf16.bf16.f32 "
        "{%0,%1,%2,%3}, {%4,%5,%6,%7}, {%8,%9}, {%0,%1,%2,%3};"
        : "+f"(c[0]), "+f"(c[1]), "+f"(c[2]), "+f"(c[3])
        : "r"(a[0]), "r"(a[1]), "r"(a[2]), "r"(a[3]), "r"(b[0]), "r"(b[1]));
}
__device__ __forceinline__ void ldsm_x4(uint32_t* r, uint32_t addr) {
    asm volatile("ldmatrix.sync.aligned.m8n8.x4.shared.b16 {%0,%1,%2,%3}, [%4];"
        : "=r"(r[0]), "=r"(r[1]), "=r"(r[2]), "=r"(r[3]) : "r"(addr));
}
__device__ __forceinline__ uint32_t pack_bf16(__nv_bfloat16 lo, __nv_bfloat16 hi) {
    return (uint32_t)__bfloat16_as_ushort(lo) | ((uint32_t)__bfloat16_as_ushort(hi) << 16);
}

// ================= P0: merged prep (xPos tables + W transpose/split) =========
__global__ void prep_kernel(const float* __restrict__ WQ,
                            const float* __restrict__ WK,
                            const float* __restrict__ WV) {
    int bid = blockIdx.x;
    int t   = threadIdx.x;
    if (bid < 512) {
        int id  = bid * 256 + t;            // 0 .. 32*4096-1
        int pr  = id >> 12;
        int pos = id & (SEQ - 1);
        float fp = (float)pos;
        float inv_freq = 1.0f / powf(10000.0f, (float)pr * (1.0f / 32.0f));
        float sv = (2.0f * pr + 0.4f * 64.0f) * (1.0f / (1.4f * 64.0f));
        float sc = powf(sv, fp * (1.0f / 512.0f));
        float sn, cs;
        sincosf(fp * inv_freq, &sn, &cs);
        float2 q, k;
        q.x = cs * sc;  q.y = sn * sc;
        float rs = 1.0f / sc;
        k.x = cs * rs;  k.y = sn * rs;
        g_qtab[pr * SEQ + pos] = q;
        g_ktab[pr * SEQ + pos] = k;
    } else {
        int n = bid - 512;                  // 0..191
        const float* W = (n < 64) ? WQ : ((n < 128) ? WK : WV);
        int cc = n & 63;
        for (int k = t; k < HID; k += 256) {
            float w = W[k * DIM + cc];
            __nv_bfloat16 h = __float2bfloat16(w);
            g_Wh[n * HID + k] = h;
            g_Wl[n * HID + k] = __float2bfloat16(w - __bfloat162float(h));
        }
    }
}

// ======== K1: HMMA bf16 split GEMM (ldmatrix frags) + xPos epilogue ==========
// D[8192 x 192] = X @ [WQ|WK|WV]; per CTA M=64, N=192; warp tile 32x48.
#define PA 40   // smem pitch in bf16 units (80B): 20-bank stride, LDSM conflict-free

__global__ __launch_bounds__(256) void gemm_kernel(const float* __restrict__ X) {
    __shared__ __nv_bfloat16 Ah[64 * PA], Al[64 * PA];
    __shared__ __nv_bfloat16 Bh[NTOT * PA], Bl[NTOT * PA];

    const int t    = threadIdx.x;
    const int wid  = t >> 5, lane = t & 31;
    const int g    = lane >> 2, tig = lane & 3;
    const int wm   = wid >> 2, wn = wid & 3;     // warp grid 2 x 4
    const int r0   = blockIdx.x * 64;

    // smem uint32 bases for ldmatrix
    const uint32_t uAh = (uint32_t)__cvta_generic_to_shared(Ah);
    const uint32_t uAl = (uint32_t)__cvta_generic_to_shared(Al);
    const uint32_t uBh = (uint32_t)__cvta_generic_to_shared(Bh);
    const uint32_t uBl = (uint32_t)__cvta_generic_to_shared(Bl);
    // per-lane ldmatrix element offsets (in bf16 units)
    const int aoff = (wm * 32 + (lane & 15)) * PA + ((lane >> 4) << 3);
    const int boff = (wn * 48 + ((lane >> 4) << 3) + (lane & 7)) * PA + (((lane >> 3) & 1) << 3);

    float C[2][6][4];
    #pragma unroll
    for (int mt = 0; mt < 2; mt++)
        #pragma unroll
        for (int nt = 0; nt < 6; nt++)
            #pragma unroll
            for (int i = 0; i < 4; i++) C[mt][nt][i] = 0.f;

    // prefetch registers
    float4 pxa[2];
    uint4  pbh[3], pbl[3];

    #pragma unroll
    for (int j = 0; j < 2; j++) {
        int id = t + 256 * j;
        pxa[j] = *(const float4*)(X + (size_t)(r0 + (id >> 3)) * HID + (id & 7) * 4);
    }
    #pragma unroll
    for (int j = 0; j < 3; j++) {
        int id = t + 256 * j;
        int n = id >> 2, k8 = (id & 3) * 8;
        pbh[j] = *(const uint4*)(g_Wh + (size_t)n * HID + k8);
        pbl[j] = *(const uint4*)(g_Wl + (size_t)n * HID + k8);
    }

    for (int c = 0; c < 32; c++) {
        __syncthreads();           // previous chunk's compute done
        // ---- store A (fp32 -> bf16 hi/lo)
        #pragma unroll
        for (int j = 0; j < 2; j++) {
            int id = t + 256 * j;
            int row = id >> 3, col4 = (id & 7) * 4;
            float4 v = pxa[j];
            __nv_bfloat16 h0 = __float2bfloat16(v.x), h1 = __float2bfloat16(v.y);
            __nv_bfloat16 h2 = __float2bfloat16(v.z), h3 = __float2bfloat16(v.w);
            __nv_bfloat16 l0 = __float2bfloat16(v.x - __bfloat162float(h0));
            __nv_bfloat16 l1 = __float2bfloat16(v.y - __bfloat162float(h1));
            __nv_bfloat16 l2 = __float2bfloat16(v.z - __bfloat162float(h2));
            __nv_bfloat16 l3 = __float2bfloat16(v.w - __bfloat162float(h3));
            *(uint2*)(Ah + row * PA + col4) = make_uint2(pack_bf16(h0, h1), pack_bf16(h2, h3));
            *(uint2*)(Al + row * PA + col4) = make_uint2(pack_bf16(l0, l1), pack_bf16(l2, l3));
        }
        #pragma unroll
        for (int j = 0; j < 3; j++) {
            int id = t + 256 * j;
            int n = id >> 2, k8 = (id & 3) * 8;
            *(uint4*)(Bh + n * PA + k8) = pbh[j];
            *(uint4*)(Bl + n * PA + k8) = pbl[j];
        }
        __syncthreads();
        // ---- prefetch chunk c+1 (overlaps compute below)
        if (c < 31) {
            int kt = (c + 1) * 32;
            #pragma unroll
            for (int j = 0; j < 2; j++) {
                int id = t + 256 * j;
                pxa[j] = *(const float4*)(X + (size_t)(r0 + (id >> 3)) * HID + kt + (id & 7) * 4);
            }
            #pragma unroll
            for (int j = 0; j < 3; j++) {
                int id = t + 256 * j;
                int n = id >> 2, k8 = (id & 3) * 8;
                pbh[j] = *(const uint4*)(g_Wh + (size_t)n * HID + kt + k8);
                pbl[j] = *(const uint4*)(g_Wl + (size_t)n * HID + kt + k8);
            }
        }
        // ---- compute: 2 k16 steps, fragments via ldmatrix
        #pragma unroll
        for (int ks = 0; ks < 2; ks++) {
            const int ko = ks * 16;
            uint32_t fah[2][4], fal[2][4];
            #pragma unroll
            for (int mt = 0; mt < 2; mt++) {
                uint32_t eo = (uint32_t)(aoff + mt * 16 * PA + ko) * 2;
                ldsm_x4(fah[mt], uAh + eo);
                ldsm_x4(fal[mt], uAl + eo);
            }
            uint32_t fbh[6][2], fbl[6][2];
            #pragma unroll
            for (int p3 = 0; p3 < 3; p3++) {
                uint32_t eo = (uint32_t)(boff + p3 * 16 * PA + ko) * 2;
                uint32_t tmp[4];
                ldsm_x4(tmp, uBh + eo);
                fbh[2*p3][0] = tmp[0]; fbh[2*p3][1] = tmp[1];
                fbh[2*p3+1][0] = tmp[2]; fbh[2*p3+1][1] = tmp[3];
                ldsm_x4(tmp, uBl + eo);
                fbl[2*p3][0] = tmp[0]; fbl[2*p3][1] = tmp[1];
                fbl[2*p3+1][0] = tmp[2]; fbl[2*p3+1][1] = tmp[3];
            }
            #pragma unroll
            for (int mt = 0; mt < 2; mt++)
                #pragma unroll
                for (int nt = 0; nt < 6; nt++) {
                    mma_bf16(C[mt][nt], fah[mt], fbh[nt]);
                    mma_bf16(C[mt][nt], fah[mt], fbl[nt]);
                    mma_bf16(C[mt][nt], fal[mt], fbh[nt]);
                }
        }
    }

    // ---------------- epilogue: xPos tables, write g_Q/g_K/g_V ---------------
    #pragma unroll
    for (int mt = 0; mt < 2; mt++) {
        int ra = r0 + wm * 32 + mt * 16 + g;
        int rb = ra + 8;
        int pa_ = ra & (SEQ - 1), pb_ = rb & (SEQ - 1);
        #pragma unroll
        for (int nt = 0; nt < 6; nt++) {
            int gc = wn * 48 + nt * 8 + tig * 2;
            float v0 = C[mt][nt][0], v1 = C[mt][nt][1];
            float v2 = C[mt][nt][2], v3 = C[mt][nt][3];
            if (gc >= 128) {               // V passthrough
                int lc = gc - 128;
                *(float2*)(g_V + (size_t)ra * DIM + lc) = make_float2(v0, v1);
                *(float2*)(g_V + (size_t)rb * DIM + lc) = make_float2(v2, v3);
            } else {                       // Q / K rotation
                const float2* tab = (gc < 64) ? g_qtab : g_ktab;
                int pr = (gc & 63) >> 1;
                float2 ta = tab[pr * SEQ + pa_];
                float2 tb = tab[pr * SEQ + pb_];
                float* dst = (gc < 64) ? g_Q : g_K;
                int lc = gc & 63;
                *(float2*)(dst + (size_t)ra * DIM + lc) =
                    make_float2(v0 * ta.x - v1 * ta.y, v1 * ta.x + v0 * ta.y);
                *(float2*)(dst + (size_t)rb * DIM + lc) =
                    make_float2(v2 * tb.x - v3 * tb.y, v3 * tb.x + v2 * tb.y);
            }
        }
    }
}

// ====== K2: per-chunk decayed outer product, 2 blocks per chunk (d-split) ====
__global__ __launch_bounds__(256) void chunk_kv_kernel() {
    __shared__ float Ks[CHUNK][DIM];
    __shared__ float Vs[CHUNK][32];
    __shared__ float w[CHUNK];
    const int t   = threadIdx.x;
    const int idx = blockIdx.x;
    const int dh  = idx & 1;
    const int c   = (idx >> 1) & (NCHUNK - 1);
    const int b   = idx >> 7;
    const int base = (b * SEQ + c * CHUNK) * DIM;

    #pragma unroll
    for (int q = 0; q < 16; q++) {
        int f = t + 256 * q;
        ((float*)Ks)[f] = g_K[base + f];
    }
    #pragma unroll
    for (int q = 0; q < 8; q++) {
        int f = t + 256 * q;              // 0..2047 -> row f>>5, col f&31
        Vs[f >> 5][f & 31] = g_V[base + (f >> 5) * DIM + dh * 32 + (f & 31)];
    }
    if (t < CHUNK) w[t] = powf(GAMMA_F, (float)(CHUNK - t));
    __syncthreads();

    const int a0 = (t >> 4) * 4;
    const int dl = (t & 15) * 2;
    float acc[4][2];
    #pragma unroll
    for (int p = 0; p < 4; p++) { acc[p][0] = 0.f; acc[p][1] = 0.f; }

    for (int j = 0; j < CHUNK; j++) {
        float wj = w[j];
        float ka[4], v0 = Vs[j][dl], v1 = Vs[j][dl + 1];
        #pragma unroll
        for (int p = 0; p < 4; p++) ka[p] = Ks[j][a0 + p] * wj;
        #pragma unroll
        for (int p = 0; p < 4; p++) {
            acc[p][0] = fmaf(ka[p], v0, acc[p][0]);
            acc[p][1] = fmaf(ka[p], v1, acc[p][1]);
        }
    }

    int gbase = (b * NCHUNK + c) * DIM * DIM;
    #pragma unroll
    for (int p = 0; p < 4; p++)
        *(float2*)(g_G + gbase + (a0 + p) * DIM + dh * 32 + dl) =
            make_float2(acc[p][0], acc[p][1]);
}

// ====== K3: elementwise scan, MLP-batched (groups of 8 independent loads) ====
__global__ __launch_bounds__(128) void scan_kernel() {
    int e = blockIdx.x * 128 + threadIdx.x;          // 0..8191
    int b  = e >> 12;
    int ed = e & (DIM * DIM - 1);
    const float g64 = powf(GAMMA_F, 64.0f);
    float acc = 0.f;
    int base = b * NCHUNK * DIM * DIM + ed;
    const float* Gp = g_G + base;
    float*       Ap = g_A + base;
    #pragma unroll
    for (int grp = 0; grp < 8; grp++) {
        float buf[8];
        #pragma unroll
        for (int u = 0; u < 8; u++)                   // 8 independent LDGs (MLP=8)
            buf[u] = Gp[(grp * 8 + u) * (DIM * DIM)];
        #pragma unroll
        for (int u = 0; u < 8; u++) {
            Ap[(grp * 8 + u) * (DIM * DIM)] = acc;    // state BEFORE chunk
            acc = acc * g64 + buf[u];
        }
    }
}

// ====== K4: out = (Q K^T .* decay) V + diag(g^i)(Q A_c); 2 blocks/chunk =====
#define SWZ(row, col) ((row) * 64 + ((col) ^ ((row) & 31)))

__global__ __launch_bounds__(256) void out_kernel(float* __restrict__ out) {
    __shared__ float Qs[32 * 64];
    __shared__ float Ks[64 * 64];   // swizzled K, then reused for V
    __shared__ float Ss[32 * 64];

    const int t    = threadIdx.x;
    const int idx  = blockIdx.x;
    const int half = idx & 1;
    const int c    = (idx >> 1) & (NCHUNK - 1);
    const int b    = idx >> 7;
    const int base  = (b * SEQ + c * CHUNK) * DIM;
    const int rbase = base + half * 32 * DIM;

    #pragma unroll
    for (int q = 0; q < 8; q++) {
        int f = t + 256 * q;
        Qs[f] = g_Q[rbase + f];
    }
    #pragma unroll
    for (int q = 0; q < 16; q++) {
        int f = t + 256 * q;
        int row = f >> 6, col = f & 63;
        Ks[SWZ(row, col)] = g_K[base + f];
    }
    __syncthreads();

    const int ti = t >> 4, tj = t & 15;
    const int i0 = ti * 2, j0 = tj * 4;

    // ---- phase 1: S = (Q K^T) .* gamma^(gi-j) causal mask
    float s[2][4];
    #pragma unroll
    for (int p = 0; p < 2; p++)
        #pragma unroll
        for (int q = 0; q < 4; q++) s[p][q] = 0.f;

    for (int a = 0; a < DIM; a++) {
        float qa[2], kb[4];
        #pragma unroll
        for (int p = 0; p < 2; p++) qa[p] = Qs[(i0 + p) * 64 + a];
        #pragma unroll
        for (int q = 0; q < 4; q++) kb[q] = Ks[SWZ(j0 + q, a)];
        #pragma unroll
        for (int p = 0; p < 2; p++)
            #pragma unroll
            for (int q = 0; q < 4; q++)
                s[p][q] = fmaf(qa[p], kb[q], s[p][q]);
    }
    #pragma unroll
    for (int p = 0; p < 2; p++) {
        int gi = half * 32 + i0 + p;
        #pragma unroll
        for (int q = 0; q < 4; q++) {
            int j = j0 + q;
            float v = (gi >= j) ? s[p][q] * exp2f(LG2G * (float)(gi - j)) : 0.f;
            Ss[(i0 + p) * 64 + j] = v;
        }
    }
    __syncthreads();

    // overwrite Ks with V (swizzled)
    #pragma unroll
    for (int q = 0; q < 16; q++) {
        int f = t + 256 * q;
        int row = f >> 6, col = f & 63;
        Ks[SWZ(row, col)] = g_V[base + f];
    }
    __syncthreads();

    // ---- phase 2: out = S V + diag * (Q A)
    const int d0 = tj * 4;
    float o[2][4];
    #pragma unroll
    for (int p = 0; p < 2; p++)
        #pragma unroll
        for (int q = 0; q < 4; q++) o[p][q] = 0.f;

    for (int j = 0; j < CHUNK; j++) {
        float sp[2], vv[4];
        #pragma unroll
        for (int p = 0; p < 2; p++) sp[p] = Ss[(i0 + p) * 64 + j];
        #pragma unroll
        for (int q = 0; q < 4; q++) vv[q] = Ks[SWZ(j, d0 + q)];
        #pragma unroll
        for (int p = 0; p < 2; p++)
            #pragma unroll
            for (int q = 0; q < 4; q++)
                o[p][q] = fmaf(sp[p], vv[q], o[p][q]);
    }

    const float* A = g_A + (b * NCHUNK + c) * DIM * DIM;
    float oa[2][4];
    #pragma unroll
    for (int p = 0; p < 2; p++)
        #pragma unroll
        for (int q = 0; q < 4; q++) oa[p][q] = 0.f;

    for (int a = 0; a < DIM; a++) {
        float4 av = *(const float4*)(A + a * DIM + d0);
        #pragma unroll
        for (int p = 0; p < 2; p++) {
            float qa = Qs[(i0 + p) * 64 + a];
            oa[p][0] = fmaf(qa, av.x, oa[p][0]);
            oa[p][1] = fmaf(qa, av.y, oa[p][1]);
            oa[p][2] = fmaf(qa, av.z, oa[p][2]);
            oa[p][3] = fmaf(qa, av.w, oa[p][3]);
        }
    }

    #pragma unroll
    for (int p = 0; p < 2; p++) {
        int gi = half * 32 + i0 + p;
        float dec = exp2f(LG2G * (float)gi);
        float4 res;
        res.x = o[p][0] + dec * oa[p][0];
        res.y = o[p][1] + dec * oa[p][1];
        res.z = o[p][2] + dec * oa[p][2];
        res.w = o[p][3] + dec * oa[p][3];
        *(float4*)(out + rbase + (i0 + p) * 64 + d0) = res;
    }
}

// ============================== launch ======================================
extern "C" void kernel_launch(void* const* d_in, const int* in_sizes, int n_in,
                              void* d_out, int out_size)
{
    const float* X  = (const float*)d_in[0];
    const float* WQ = (const float*)d_in[1];
    const float* WK = (const float*)d_in[2];
    const float* WV = (const float*)d_in[3];
    float* out = (float*)d_out;

    prep_kernel<<<512 + NTOT, 256>>>(WQ, WK, WV);
    gemm_kernel<<<NROWS / 64, 256>>>(X);
    chunk_kv_kernel<<<BATCH * NCHUNK * 2, 256>>>();
    scan_kernel<<<(BATCH * DIM * DIM) / 128, 128>>>();
    out_kernel<<<BATCH * NCHUNK * 2, 256>>>(out);
}

// round 10
// speedup vs baseline: 2.2686x; 1.1387x over previous
#include <cuda_runtime.h>
#include <cuda_fp16.h>
#include <cstdint>
#include <math.h>

#define BATCH 2
#define SEQ   4096
#define HID   1024
#define DIM   64
#define CHUNK 64
#define NCHUNK (SEQ/CHUNK)
#define NROWS (BATCH*SEQ)
#define GAMMA_F 0.96875f
#define NTOT 192
#define LG2G (-0.045803689613124785f) // log2(0.96875)
#define WSCALE 1024.0f
#define INV_WSCALE (1.0f/1024.0f)

// ---------------- scratch (static device globals; no runtime alloc) ----------
__device__ __half g_Wh[NTOT*HID];          // W^T * 1024: [n][k], fp16 hi
__device__ __half g_Wl[NTOT*HID];          // fp16 lo residual
__device__ float2 g_qtab[32*SEQ];          // (cos*sc, sin*sc) [pr][pos]
__device__ float2 g_ktab[32*SEQ];          // (cos/sc, sin/sc)
__device__ float g_Q[NROWS*DIM];
__device__ float g_K[NROWS*DIM];
__device__ float g_V[NROWS*DIM];
__device__ float g_G[BATCH*NCHUNK*DIM*DIM];
__device__ float g_A[BATCH*NCHUNK*DIM*DIM];

// ---------------- warp-level fp16 MMA + ldmatrix (sm_75+/80+) ----------------
__device__ __forceinline__ void mma_fp16(float* c, const uint32_t* a, const uint32_t* b) {
    asm volatile(
        "mma.sync.aligned.m16n8k16.row.col.f32.f16.f16.f32 "
        "{%0,%1,%2,%3}, {%4,%5,%6,%7}, {%8,%9}, {%0,%1,%2,%3};"
        : "+f"(c[0]), "+f"(c[1]), "+f"(c[2]), "+f"(c[3])
        : "r"(a[0]), "r"(a[1]), "r"(a[2]), "r"(a[3]), "r"(b[0]), "r"(b[1]));
}
__device__ __forceinline__ void ldsm_x4(uint32_t* r, uint32_t addr) {
    asm volatile("ldmatrix.sync.aligned.m8n8.x4.shared.b16 {%0,%1,%2,%3}, [%4];"
        : "=r"(r[0]), "=r"(r[1]), "=r"(r[2]), "=r"(r[3]) : "r"(addr));
}
__device__ __forceinline__ uint32_t pack_h2(__half lo, __half hi) {
    return (uint32_t)__half_as_ushort(lo) | ((uint32_t)__half_as_ushort(hi) << 16);
}

// ================= P0: merged prep (xPos tables + W transpose/split) =========
__global__ void prep_kernel(const float* __restrict__ WQ,
                            const float* __restrict__ WK,
                            const float* __restrict__ WV) {
    int bid = blockIdx.x;
    int t   = threadIdx.x;
    if (bid < 512) {
        int id  = bid * 256 + t;            // 0 .. 32*4096-1
        int pr  = id >> 12;
        int pos = id & (SEQ - 1);
        float fp = (float)pos;
        float inv_freq = 1.0f / powf(10000.0f, (float)pr * (1.0f / 32.0f));
        float sv = (2.0f * pr + 0.4f * 64.0f) * (1.0f / (1.4f * 64.0f));
        float sc = powf(sv, fp * (1.0f / 512.0f));
        float sn, cs;
        sincosf(fp * inv_freq, &sn, &cs);
        float2 q, k;
        q.x = cs * sc;  q.y = sn * sc;
        float rs = 1.0f / sc;
        k.x = cs * rs;  k.y = sn * rs;
        g_qtab[pr * SEQ + pos] = q;
        g_ktab[pr * SEQ + pos] = k;
    } else {
        int n = bid - 512;                  // 0..191
        const float* W = (n < 64) ? WQ : ((n < 128) ? WK : WV);
        int cc = n & 63;
        for (int k = t; k < HID; k += 256) {
            float w = W[k * DIM + cc] * WSCALE;   // exact scale (pow2)
            __half h = __float2half(w);
            g_Wh[n * HID + k] = h;
            g_Wl[n * HID + k] = __float2half(w - __half2float(h));
        }
    }
}

// ===== K1: HMMA fp16 2-term GEMM (W pre-scaled; ldmatrix) + xPos epilogue ====
// D[8192 x 192] = X @ [WQ|WK|WV]*1024; per CTA M=64, N=192; warp tile 32x48.
#define PA 40   // smem pitch in fp16 units (80B): 20-bank stride, LDSM conflict-free

__global__ __launch_bounds__(256) void gemm_kernel(const float* __restrict__ X) {
    __shared__ __half Ah[64 * PA];
    __shared__ __half Bh[NTOT * PA], Bl[NTOT * PA];

    const int t    = threadIdx.x;
    const int wid  = t >> 5, lane = t & 31;
    const int g    = lane >> 2, tig = lane & 3;
    const int wm   = wid >> 2, wn = wid & 3;     // warp grid 2 x 4
    const int r0   = blockIdx.x * 64;

    const uint32_t uAh = (uint32_t)__cvta_generic_to_shared(Ah);
    const uint32_t uBh = (uint32_t)__cvta_generic_to_shared(Bh);
    const uint32_t uBl = (uint32_t)__cvta_generic_to_shared(Bl);
    // per-lane ldmatrix element offsets (in fp16 units)
    const int aoff = (wm * 32 + (lane & 15)) * PA + ((lane >> 4) << 3);
    const int boff = (wn * 48 + ((lane >> 4) << 3) + (lane & 7)) * PA + (((lane >> 3) & 1) << 3);

    float C[2][6][4];
    #pragma unroll
    for (int mt = 0; mt < 2; mt++)
        #pragma unroll
        for (int nt = 0; nt < 6; nt++)
            #pragma unroll
            for (int i = 0; i < 4; i++) C[mt][nt][i] = 0.f;

    // prefetch registers
    float4 pxa[2];
    uint4  pbh[3], pbl[3];

    #pragma unroll
    for (int j = 0; j < 2; j++) {
        int id = t + 256 * j;
        pxa[j] = *(const float4*)(X + (size_t)(r0 + (id >> 3)) * HID + (id & 7) * 4);
    }
    #pragma unroll
    for (int j = 0; j < 3; j++) {
        int id = t + 256 * j;
        int n = id >> 2, k8 = (id & 3) * 8;
        pbh[j] = *(const uint4*)(g_Wh + (size_t)n * HID + k8);
        pbl[j] = *(const uint4*)(g_Wl + (size_t)n * HID + k8);
    }

    for (int c = 0; c < 32; c++) {
        __syncthreads();           // previous chunk's compute done
        // ---- store A (fp32 -> fp16, no residual)
        #pragma unroll
        for (int j = 0; j < 2; j++) {
            int id = t + 256 * j;
            int row = id >> 3, col4 = (id & 7) * 4;
            float4 v = pxa[j];
            *(uint2*)(Ah + row * PA + col4) =
                make_uint2(pack_h2(__float2half(v.x), __float2half(v.y)),
                           pack_h2(__float2half(v.z), __float2half(v.w)));
        }
        #pragma unroll
        for (int j = 0; j < 3; j++) {
            int id = t + 256 * j;
            int n = id >> 2, k8 = (id & 3) * 8;
            *(uint4*)(Bh + n * PA + k8) = pbh[j];
            *(uint4*)(Bl + n * PA + k8) = pbl[j];
        }
        __syncthreads();
        // ---- prefetch chunk c+1 (overlaps compute below)
        if (c < 31) {
            int kt = (c + 1) * 32;
            #pragma unroll
            for (int j = 0; j < 2; j++) {
                int id = t + 256 * j;
                pxa[j] = *(const float4*)(X + (size_t)(r0 + (id >> 3)) * HID + kt + (id & 7) * 4);
            }
            #pragma unroll
            for (int j = 0; j < 3; j++) {
                int id = t + 256 * j;
                int n = id >> 2, k8 = (id & 3) * 8;
                pbh[j] = *(const uint4*)(g_Wh + (size_t)n * HID + kt + k8);
                pbl[j] = *(const uint4*)(g_Wl + (size_t)n * HID + kt + k8);
            }
        }
        // ---- compute: 2 k16 steps, fragments via ldmatrix
        #pragma unroll
        for (int ks = 0; ks < 2; ks++) {
            const int ko = ks * 16;
            uint32_t fah[2][4];
            #pragma unroll
            for (int mt = 0; mt < 2; mt++)
                ldsm_x4(fah[mt], uAh + (uint32_t)(aoff + mt * 16 * PA + ko) * 2);
            uint32_t fbh[6][2], fbl[6][2];
            #pragma unroll
            for (int p3 = 0; p3 < 3; p3++) {
                uint32_t eo = (uint32_t)(boff + p3 * 16 * PA + ko) * 2;
                uint32_t tmp[4];
                ldsm_x4(tmp, uBh + eo);
                fbh[2*p3][0] = tmp[0]; fbh[2*p3][1] = tmp[1];
                fbh[2*p3+1][0] = tmp[2]; fbh[2*p3+1][1] = tmp[3];
                ldsm_x4(tmp, uBl + eo);
                fbl[2*p3][0] = tmp[0]; fbl[2*p3][1] = tmp[1];
                fbl[2*p3+1][0] = tmp[2]; fbl[2*p3+1][1] = tmp[3];
            }
            #pragma unroll
            for (int mt = 0; mt < 2; mt++)
                #pragma unroll
                for (int nt = 0; nt < 6; nt++) {
                    mma_fp16(C[mt][nt], fah[mt], fbh[nt]);
                    mma_fp16(C[mt][nt], fah[mt], fbl[nt]);
                }
        }
    }

    // -------- epilogue: undo WSCALE, xPos tables, write g_Q/g_K/g_V ----------
    #pragma unroll
    for (int mt = 0; mt < 2; mt++) {
        int ra = r0 + wm * 32 + mt * 16 + g;
        int rb = ra + 8;
        int pa_ = ra & (SEQ - 1), pb_ = rb & (SEQ - 1);
        #pragma unroll
        for (int nt = 0; nt < 6; nt++) {
            int gc = wn * 48 + nt * 8 + tig * 2;
            float v0 = C[mt][nt][0] * INV_WSCALE, v1 = C[mt][nt][1] * INV_WSCALE;
            float v2 = C[mt][nt][2] * INV_WSCALE, v3 = C[mt][nt][3] * INV_WSCALE;
            if (gc >= 128) {               // V passthrough
                int lc = gc - 128;
                *(float2*)(g_V + (size_t)ra * DIM + lc) = make_float2(v0, v1);
                *(float2*)(g_V + (size_t)rb * DIM + lc) = make_float2(v2, v3);
            } else {                       // Q / K rotation
                const float2* tab = (gc < 64) ? g_qtab : g_ktab;
                int pr = (gc & 63) >> 1;
                float2 ta = tab[pr * SEQ + pa_];
                float2 tb = tab[pr * SEQ + pb_];
                float* dst = (gc < 64) ? g_Q : g_K;
                int lc = gc & 63;
                *(float2*)(dst + (size_t)ra * DIM + lc) =
                    make_float2(v0 * ta.x - v1 * ta.y, v1 * ta.x + v0 * ta.y);
                *(float2*)(dst + (size_t)rb * DIM + lc) =
                    make_float2(v2 * tb.x - v3 * tb.y, v3 * tb.x + v2 * tb.y);
            }
        }
    }
}

// ====== K2: per-chunk decayed outer product, 2 blocks per chunk (d-split) ====
__global__ __launch_bounds__(256) void chunk_kv_kernel() {
    __shared__ float Ks[CHUNK][DIM];
    __shared__ float Vs[CHUNK][32];
    __shared__ float w[CHUNK];
    const int t   = threadIdx.x;
    const int idx = blockIdx.x;
    const int dh  = idx & 1;
    const int c   = (idx >> 1) & (NCHUNK - 1);
    const int b   = idx >> 7;
    const int base = (b * SEQ + c * CHUNK) * DIM;

    #pragma unroll
    for (int q = 0; q < 16; q++) {
        int f = t + 256 * q;
        ((float*)Ks)[f] = g_K[base + f];
    }
    #pragma unroll
    for (int q = 0; q < 8; q++) {
        int f = t + 256 * q;              // 0..2047 -> row f>>5, col f&31
        Vs[f >> 5][f & 31] = g_V[base + (f >> 5) * DIM + dh * 32 + (f & 31)];
    }
    if (t < CHUNK) w[t] = powf(GAMMA_F, (float)(CHUNK - t));
    __syncthreads();

    const int a0 = (t >> 4) * 4;
    const int dl = (t & 15) * 2;
    float acc[4][2];
    #pragma unroll
    for (int p = 0; p < 4; p++) { acc[p][0] = 0.f; acc[p][1] = 0.f; }

    for (int j = 0; j < CHUNK; j++) {
        float wj = w[j];
        float ka[4], v0 = Vs[j][dl], v1 = Vs[j][dl + 1];
        #pragma unroll
        for (int p = 0; p < 4; p++) ka[p] = Ks[j][a0 + p] * wj;
        #pragma unroll
        for (int p = 0; p < 4; p++) {
            acc[p][0] = fmaf(ka[p], v0, acc[p][0]);
            acc[p][1] = fmaf(ka[p], v1, acc[p][1]);
        }
    }

    int gbase = (b * NCHUNK + c) * DIM * DIM;
    #pragma unroll
    for (int p = 0; p < 4; p++)
        *(float2*)(g_G + gbase + (a0 + p) * DIM + dh * 32 + dl) =
            make_float2(acc[p][0], acc[p][1]);
}

// ============ K3: elementwise scan, full MLP=64 (one exposed wait) ===========
__global__ __launch_bounds__(128) void scan_kernel() {
    int e = blockIdx.x * 128 + threadIdx.x;          // 0..8191
    int b  = e >> 12;
    int ed = e & (DIM * DIM - 1);
    const float g64 = powf(GAMMA_F, 64.0f);
    int base = b * NCHUNK * DIM * DIM + ed;
    const float* Gp = g_G + base;
    float*       Ap = g_A + base;
    float buf[NCHUNK];
    #pragma unroll
    for (int u = 0; u < NCHUNK; u++)                 // 64 independent LDGs
        buf[u] = Gp[u * (DIM * DIM)];
    float acc = 0.f;
    #pragma unroll
    for (int u = 0; u < NCHUNK; u++) {
        Ap[u * (DIM * DIM)] = acc;                   // state BEFORE chunk
        acc = acc * g64 + buf[u];
    }
}

// ====== K4: out = (Q K^T .* decay) V + diag(g^i)(Q A_c); 2 blocks/chunk =====
#define SWZ(row, col) ((row) * 64 + ((col) ^ ((row) & 31)))

__global__ __launch_bounds__(256) void out_kernel(float* __restrict__ out) {
    __shared__ float Qs[32 * 64];
    __shared__ float Ks[64 * 64];   // swizzled K, then reused for V
    __shared__ float Ss[32 * 64];

    const int t    = threadIdx.x;
    const int idx  = blockIdx.x;
    const int half = idx & 1;
    const int c    = (idx >> 1) & (NCHUNK - 1);
    const int b    = idx >> 7;
    const int base  = (b * SEQ + c * CHUNK) * DIM;
    const int rbase = base + half * 32 * DIM;

    #pragma unroll
    for (int q = 0; q < 8; q++) {
        int f = t + 256 * q;
        Qs[f] = g_Q[rbase + f];
    }
    #pragma unroll
    for (int q = 0; q < 16; q++) {
        int f = t + 256 * q;
        int row = f >> 6, col = f & 63;
        Ks[SWZ(row, col)] = g_K[base + f];
    }
    __syncthreads();

    const int ti = t >> 4, tj = t & 15;
    const int i0 = ti * 2, j0 = tj * 4;

    // ---- phase 1: S = (Q K^T) .* gamma^(gi-j) causal mask
    float s[2][4];
    #pragma unroll
    for (int p = 0; p < 2; p++)
        #pragma unroll
        for (int q = 0; q < 4; q++) s[p][q] = 0.f;

    for (int a = 0; a < DIM; a++) {
        float qa[2], kb[4];
        #pragma unroll
        for (int p = 0; p < 2; p++) qa[p] = Qs[(i0 + p) * 64 + a];
        #pragma unroll
        for (int q = 0; q < 4; q++) kb[q] = Ks[SWZ(j0 + q, a)];
        #pragma unroll
        for (int p = 0; p < 2; p++)
            #pragma unroll
            for (int q = 0; q < 4; q++)
                s[p][q] = fmaf(qa[p], kb[q], s[p][q]);
    }
    #pragma unroll
    for (int p = 0; p < 2; p++) {
        int gi = half * 32 + i0 + p;
        #pragma unroll
        for (int q = 0; q < 4; q++) {
            int j = j0 + q;
            float v = (gi >= j) ? s[p][q] * exp2f(LG2G * (float)(gi - j)) : 0.f;
            Ss[(i0 + p) * 64 + j] = v;
        }
    }
    __syncthreads();

    // overwrite Ks with V (swizzled)
    #pragma unroll
    for (int q = 0; q < 16; q++) {
        int f = t + 256 * q;
        int row = f >> 6, col = f & 63;
        Ks[SWZ(row, col)] = g_V[base + f];
    }
    __syncthreads();

    // ---- phase 2: out = S V + diag * (Q A)
    const int d0 = tj * 4;
    float o[2][4];
    #pragma unroll
    for (int p = 0; p < 2; p++)
        #pragma unroll
        for (int q = 0; q < 4; q++) o[p][q] = 0.f;

    for (int j = 0; j < CHUNK; j++) {
        float sp[2], vv[4];
        #pragma unroll
        for (int p = 0; p < 2; p++) sp[p] = Ss[(i0 + p) * 64 + j];
        #pragma unroll
        for (int q = 0; q < 4; q++) vv[q] = Ks[SWZ(j, d0 + q)];
        #pragma unroll
        for (int p = 0; p < 2; p++)
            #pragma unroll
            for (int q = 0; q < 4; q++)
                o[p][q] = fmaf(sp[p], vv[q], o[p][q]);
    }

    const float* A = g_A + (b * NCHUNK + c) * DIM * DIM;
    float oa[2][4];
    #pragma unroll
    for (int p = 0; p < 2; p++)
        #pragma unroll
        for (int q = 0; q < 4; q++) oa[p][q] = 0.f;

    for (int a = 0; a < DIM; a++) {
        float4 av = *(const float4*)(A + a * DIM + d0);
        #pragma unroll
        for (int p = 0; p < 2; p++) {
            float qa = Qs[(i0 + p) * 64 + a];
            oa[p][0] = fmaf(qa, av.x, oa[p][0]);
            oa[p][1] = fmaf(qa, av.y, oa[p][1]);
            oa[p][2] = fmaf(qa, av.z, oa[p][2]);
            oa[p][3] = fmaf(qa, av.w, oa[p][3]);
        }
    }

    #pragma unroll
    for (int p = 0; p < 2; p++) {
        int gi = half * 32 + i0 + p;
        float dec = exp2f(LG2G * (float)gi);
        float4 res;
        res.x = o[p][0] + dec * oa[p][0];
        res.y = o[p][1] + dec * oa[p][1];
        res.z = o[p][2] + dec * oa[p][2];
        res.w = o[p][3] + dec * oa[p][3];
        *(float4*)(out + rbase + (i0 + p) * 64 + d0) = res;
    }
}

// ============================== launch ======================================
extern "C" void kernel_launch(void* const* d_in, const int* in_sizes, int n_in,
                              void* d_out, int out_size)
{
    const float* X  = (const float*)d_in[0];
    const float* WQ = (const float*)d_in[1];
    const float* WK = (const float*)d_in[2];
    const float* WV = (const float*)d_in[3];
    float* out = (float*)d_out;

    prep_kernel<<<512 + NTOT, 256>>>(WQ, WK, WV);
    gemm_kernel<<<NROWS / 64, 256>>>(X);
    chunk_kv_kernel<<<BATCH * NCHUNK * 2, 256>>>();
    scan_kernel<<<(BATCH * DIM * DIM) / 128, 128>>>();
    out_kernel<<<BATCH * NCHUNK * 2, 256>>>(out);
}

// round 11
// speedup vs baseline: 2.4785x; 1.0925x over previous
#include <cuda_runtime.h>
#include <cuda_fp16.h>
#include <cstdint>
#include <math.h>

#define BATCH 2
#define SEQ   4096
#define HID   1024
#define DIM   64
#define CHUNK 64
#define NCHUNK (SEQ/CHUNK)
#define NROWS (BATCH*SEQ)
#define GAMMA_F 0.96875f
#define NTOT 192
#define LG2G (-0.045803689613124785f) // log2(0.96875)
#define WSCALE 1024.0f
#define INV_WSCALE (1.0f/1024.0f)

// ---------------- scratch (static device globals; no runtime alloc) ----------
__device__ __half g_Wh[NTOT*HID];          // W^T * 1024: [n][k], fp16 hi
__device__ __half g_Wl[NTOT*HID];          // fp16 lo residual
__device__ float2 g_qtab[32*SEQ];          // (cos*sc, sin*sc) [pr][pos]
__device__ float2 g_ktab[32*SEQ];          // (cos/sc, sin/sc)
__device__ float g_Q[NROWS*DIM];
__device__ float g_K[NROWS*DIM];
__device__ float g_V[NROWS*DIM];
__device__ float g_G[BATCH*NCHUNK*DIM*DIM];
__device__ float g_A[BATCH*NCHUNK*DIM*DIM];

// ---------------- warp-level fp16 MMA + ldmatrix (sm_75+/80+) ----------------
__device__ __forceinline__ void mma_fp16(float* c, const uint32_t* a, const uint32_t* b) {
    asm volatile(
        "mma.sync.aligned.m16n8k16.row.col.f32.f16.f16.f32 "
        "{%0,%1,%2,%3}, {%4,%5,%6,%7}, {%8,%9}, {%0,%1,%2,%3};"
        : "+f"(c[0]), "+f"(c[1]), "+f"(c[2]), "+f"(c[3])
        : "r"(a[0]), "r"(a[1]), "r"(a[2]), "r"(a[3]), "r"(b[0]), "r"(b[1]));
}
__device__ __forceinline__ void ldsm_x4(uint32_t* r, uint32_t addr) {
    asm volatile("ldmatrix.sync.aligned.m8n8.x4.shared.b16 {%0,%1,%2,%3}, [%4];"
        : "=r"(r[0]), "=r"(r[1]), "=r"(r[2]), "=r"(r[3]) : "r"(addr));
}
__device__ __forceinline__ uint32_t pack_h2(__half lo, __half hi) {
    return (uint32_t)__half_as_ushort(lo) | ((uint32_t)__half_as_ushort(hi) << 16);
}

// ================= P0: merged prep (xPos tables + W transpose/split) =========
__global__ void prep_kernel(const float* __restrict__ WQ,
                            const float* __restrict__ WK,
                            const float* __restrict__ WV) {
    int bid = blockIdx.x;
    int t   = threadIdx.x;
    if (bid < 512) {
        int id  = bid * 256 + t;            // 0 .. 32*4096-1
        int pr  = id >> 12;
        int pos = id & (SEQ - 1);
        float fp = (float)pos;
        float inv_freq = 1.0f / powf(10000.0f, (float)pr * (1.0f / 32.0f));
        float sv = (2.0f * pr + 0.4f * 64.0f) * (1.0f / (1.4f * 64.0f));
        float sc = powf(sv, fp * (1.0f / 512.0f));
        float sn, cs;
        sincosf(fp * inv_freq, &sn, &cs);
        float2 q, k;
        q.x = cs * sc;  q.y = sn * sc;
        float rs = 1.0f / sc;
        k.x = cs * rs;  k.y = sn * rs;
        g_qtab[pr * SEQ + pos] = q;
        g_ktab[pr * SEQ + pos] = k;
    } else {
        int n = bid - 512;                  // 0..191
        const float* W = (n < 64) ? WQ : ((n < 128) ? WK : WV);
        int cc = n & 63;
        for (int k = t; k < HID; k += 256) {
            float w = W[k * DIM + cc] * WSCALE;   // exact scale (pow2)
            __half h = __float2half(w);
            g_Wh[n * HID + k] = h;
            g_Wl[n * HID + k] = __float2half(w - __half2float(h));
        }
    }
}

// ===== K1: HMMA fp16 2-term GEMM, K-chunk=64, dynamic smem, xPos epilogue ====
// D[8192 x 192] = X @ [WQ|WK|WV]*1024; per CTA M=64, N=192; warp tile 32x48.
#define PA2 72   // smem pitch in fp16 units (144B = 36 banks): LDSM conflict-free
#define OFF_A  0
#define OFF_BH (64 * PA2 * 2)                       // 9216
#define OFF_BL (OFF_BH + NTOT * PA2 * 2)            // 36864
#define GEMM_SMEM (OFF_BL + NTOT * PA2 * 2)         // 64512

__global__ __launch_bounds__(256) void gemm_kernel(const float* __restrict__ X) {
    extern __shared__ char smp[];
    __half* Ah = (__half*)(smp + OFF_A);
    __half* Bh = (__half*)(smp + OFF_BH);
    __half* Bl = (__half*)(smp + OFF_BL);

    const int t    = threadIdx.x;
    const int wid  = t >> 5, lane = t & 31;
    const int g    = lane >> 2, tig = lane & 3;
    const int wm   = wid >> 2, wn = wid & 3;     // warp grid 2 x 4
    const int r0   = blockIdx.x * 64;

    const uint32_t uAh = (uint32_t)__cvta_generic_to_shared(Ah);
    const uint32_t uBh = (uint32_t)__cvta_generic_to_shared(Bh);
    const uint32_t uBl = (uint32_t)__cvta_generic_to_shared(Bl);
    // per-lane ldmatrix element offsets (in fp16 units)
    const int aoff = (wm * 32 + (lane & 15)) * PA2 + ((lane >> 4) << 3);
    const int boff = (wn * 48 + ((lane >> 4) << 3) + (lane & 7)) * PA2 + (((lane >> 3) & 1) << 3);

    float C[2][6][4];
    #pragma unroll
    for (int mt = 0; mt < 2; mt++)
        #pragma unroll
        for (int nt = 0; nt < 6; nt++)
            #pragma unroll
            for (int i = 0; i < 4; i++) C[mt][nt][i] = 0.f;

    // prefetch registers: A 4 float4, B 6+6 uint4
    float4 pxa[4];
    uint4  pbh[6], pbl[6];

    #pragma unroll
    for (int j = 0; j < 4; j++) {
        int id = t + 256 * j;
        pxa[j] = *(const float4*)(X + (size_t)(r0 + (id >> 4)) * HID + (id & 15) * 4);
    }
    #pragma unroll
    for (int j = 0; j < 6; j++) {
        int id = t + 256 * j;
        int n = id >> 3, k8 = (id & 7) * 8;
        pbh[j] = *(const uint4*)(g_Wh + (size_t)n * HID + k8);
        pbl[j] = *(const uint4*)(g_Wl + (size_t)n * HID + k8);
    }

    for (int c = 0; c < 16; c++) {
        __syncthreads();           // previous chunk's compute done
        // ---- store A (fp32 -> fp16)
        #pragma unroll
        for (int j = 0; j < 4; j++) {
            int id = t + 256 * j;
            int row = id >> 4, col4 = (id & 15) * 4;
            float4 v = pxa[j];
            *(uint2*)(Ah + row * PA2 + col4) =
                make_uint2(pack_h2(__float2half(v.x), __float2half(v.y)),
                           pack_h2(__float2half(v.z), __float2half(v.w)));
        }
        #pragma unroll
        for (int j = 0; j < 6; j++) {
            int id = t + 256 * j;
            int n = id >> 3, k8 = (id & 7) * 8;
            *(uint4*)(Bh + n * PA2 + k8) = pbh[j];
            *(uint4*)(Bl + n * PA2 + k8) = pbl[j];
        }
        __syncthreads();
        // ---- prefetch chunk c+1 (overlaps compute below)
        if (c < 15) {
            int kt = (c + 1) * 64;
            #pragma unroll
            for (int j = 0; j < 4; j++) {
                int id = t + 256 * j;
                pxa[j] = *(const float4*)(X + (size_t)(r0 + (id >> 4)) * HID + kt + (id & 15) * 4);
            }
            #pragma unroll
            for (int j = 0; j < 6; j++) {
                int id = t + 256 * j;
                int n = id >> 3, k8 = (id & 7) * 8;
                pbh[j] = *(const uint4*)(g_Wh + (size_t)n * HID + kt + k8);
                pbl[j] = *(const uint4*)(g_Wl + (size_t)n * HID + kt + k8);
            }
        }
        // ---- compute: 4 k16 steps, fragments via ldmatrix
        #pragma unroll
        for (int ks = 0; ks < 4; ks++) {
            const int ko = ks * 16;
            uint32_t fah[2][4];
            #pragma unroll
            for (int mt = 0; mt < 2; mt++)
                ldsm_x4(fah[mt], uAh + (uint32_t)(aoff + mt * 16 * PA2 + ko) * 2);
            uint32_t fbh[6][2], fbl[6][2];
            #pragma unroll
            for (int p3 = 0; p3 < 3; p3++) {
                uint32_t eo = (uint32_t)(boff + p3 * 16 * PA2 + ko) * 2;
                uint32_t tmp[4];
                ldsm_x4(tmp, uBh + eo);
                fbh[2*p3][0] = tmp[0]; fbh[2*p3][1] = tmp[1];
                fbh[2*p3+1][0] = tmp[2]; fbh[2*p3+1][1] = tmp[3];
                ldsm_x4(tmp, uBl + eo);
                fbl[2*p3][0] = tmp[0]; fbl[2*p3][1] = tmp[1];
                fbl[2*p3+1][0] = tmp[2]; fbl[2*p3+1][1] = tmp[3];
            }
            #pragma unroll
            for (int mt = 0; mt < 2; mt++)
                #pragma unroll
                for (int nt = 0; nt < 6; nt++) {
                    mma_fp16(C[mt][nt], fah[mt], fbh[nt]);
                    mma_fp16(C[mt][nt], fah[mt], fbl[nt]);
                }
        }
    }

    // -------- epilogue: undo WSCALE, xPos tables, write g_Q/g_K/g_V ----------
    #pragma unroll
    for (int mt = 0; mt < 2; mt++) {
        int ra = r0 + wm * 32 + mt * 16 + g;
        int rb = ra + 8;
        int pa_ = ra & (SEQ - 1), pb_ = rb & (SEQ - 1);
        #pragma unroll
        for (int nt = 0; nt < 6; nt++) {
            int gc = wn * 48 + nt * 8 + tig * 2;
            float v0 = C[mt][nt][0] * INV_WSCALE, v1 = C[mt][nt][1] * INV_WSCALE;
            float v2 = C[mt][nt][2] * INV_WSCALE, v3 = C[mt][nt][3] * INV_WSCALE;
            if (gc >= 128) {               // V passthrough
                int lc = gc - 128;
                *(float2*)(g_V + (size_t)ra * DIM + lc) = make_float2(v0, v1);
                *(float2*)(g_V + (size_t)rb * DIM + lc) = make_float2(v2, v3);
            } else {                       // Q / K rotation
                const float2* tab = (gc < 64) ? g_qtab : g_ktab;
                int pr = (gc & 63) >> 1;
                float2 ta = tab[pr * SEQ + pa_];
                float2 tb = tab[pr * SEQ + pb_];
                float* dst = (gc < 64) ? g_Q : g_K;
                int lc = gc & 63;
                *(float2*)(dst + (size_t)ra * DIM + lc) =
                    make_float2(v0 * ta.x - v1 * ta.y, v1 * ta.x + v0 * ta.y);
                *(float2*)(dst + (size_t)rb * DIM + lc) =
                    make_float2(v2 * tb.x - v3 * tb.y, v3 * tb.x + v2 * tb.y);
            }
        }
    }
}

// ====== K2: per-chunk decayed outer product, 2 blocks per chunk (d-split) ====
__global__ __launch_bounds__(256) void chunk_kv_kernel() {
    __shared__ float Ks[CHUNK][DIM];
    __shared__ float Vs[CHUNK][32];
    __shared__ float w[CHUNK];
    const int t   = threadIdx.x;
    const int idx = blockIdx.x;
    const int dh  = idx & 1;
    const int c   = (idx >> 1) & (NCHUNK - 1);
    const int b   = idx >> 7;
    const int base = (b * SEQ + c * CHUNK) * DIM;

    #pragma unroll
    for (int q = 0; q < 16; q++) {
        int f = t + 256 * q;
        ((float*)Ks)[f] = g_K[base + f];
    }
    #pragma unroll
    for (int q = 0; q < 8; q++) {
        int f = t + 256 * q;              // 0..2047 -> row f>>5, col f&31
        Vs[f >> 5][f & 31] = g_V[base + (f >> 5) * DIM + dh * 32 + (f & 31)];
    }
    if (t < CHUNK) w[t] = powf(GAMMA_F, (float)(CHUNK - t));
    __syncthreads();

    const int a0 = (t >> 4) * 4;
    const int dl = (t & 15) * 2;
    float acc[4][2];
    #pragma unroll
    for (int p = 0; p < 4; p++) { acc[p][0] = 0.f; acc[p][1] = 0.f; }

    for (int j = 0; j < CHUNK; j++) {
        float wj = w[j];
        float ka[4], v0 = Vs[j][dl], v1 = Vs[j][dl + 1];
        #pragma unroll
        for (int p = 0; p < 4; p++) ka[p] = Ks[j][a0 + p] * wj;
        #pragma unroll
        for (int p = 0; p < 4; p++) {
            acc[p][0] = fmaf(ka[p], v0, acc[p][0]);
            acc[p][1] = fmaf(ka[p], v1, acc[p][1]);
        }
    }

    int gbase = (b * NCHUNK + c) * DIM * DIM;
    #pragma unroll
    for (int p = 0; p < 4; p++)
        *(float2*)(g_G + gbase + (a0 + p) * DIM + dh * 32 + dl) =
            make_float2(acc[p][0], acc[p][1]);
}

// ============ K3: elementwise scan, full MLP=64 (one exposed wait) ===========
__global__ __launch_bounds__(128) void scan_kernel() {
    int e = blockIdx.x * 128 + threadIdx.x;          // 0..8191
    int b  = e >> 12;
    int ed = e & (DIM * DIM - 1);
    const float g64 = powf(GAMMA_F, 64.0f);
    int base = b * NCHUNK * DIM * DIM + ed;
    const float* Gp = g_G + base;
    float*       Ap = g_A + base;
    float buf[NCHUNK];
    #pragma unroll
    for (int u = 0; u < NCHUNK; u++)                 // 64 independent LDGs
        buf[u] = Gp[u * (DIM * DIM)];
    float acc = 0.f;
    #pragma unroll
    for (int u = 0; u < NCHUNK; u++) {
        Ap[u * (DIM * DIM)] = acc;                   // state BEFORE chunk
        acc = acc * g64 + buf[u];
    }
}

// == K4: out = (Q K^T .* decay) V + diag(g^i)(Q A_c); transposed smem, vec LDS
#define PQ 34   // Qt/St pitch (floats): float2-aligned, conflict-free
#define PK 68   // Kt/Vt pitch (floats): float4-aligned, conflict-free loads

__global__ __launch_bounds__(256) void out_kernel(float* __restrict__ out) {
    __shared__ float Qt[64 * PQ];   // [a][i]  a=0..63, i=0..31
    __shared__ float Kt[64 * PK];   // [a][j], reused as V [j][d] in phase 2
    __shared__ float St[64 * PQ];   // [j][i]

    const int t    = threadIdx.x;
    const int idx  = blockIdx.x;
    const int half = idx & 1;
    const int c    = (idx >> 1) & (NCHUNK - 1);
    const int b    = idx >> 7;
    const int base  = (b * SEQ + c * CHUNK) * DIM;
    const int rbase = base + half * 32 * DIM;

    // Qt[a][i] = Q[rbase + i*64 + a]; Kt[a][j] = K[base + j*64 + a]
    #pragma unroll
    for (int q = 0; q < 8; q++) {
        int f = t + 256 * q;                 // i = f>>6, a = f&63
        Qt[(f & 63) * PQ + (f >> 6)] = g_Q[rbase + f];
    }
    #pragma unroll
    for (int q = 0; q < 16; q++) {
        int f = t + 256 * q;                 // j = f>>6, a = f&63
        Kt[(f & 63) * PK + (f >> 6)] = g_K[base + f];
    }
    __syncthreads();

    const int ti = t >> 4, tj = t & 15;
    const int i0 = ti * 2, j0 = tj * 4;

    // ---- phase 1: S = (Q K^T) .* gamma^(gi-j) causal mask
    float s[2][4];
    #pragma unroll
    for (int p = 0; p < 2; p++)
        #pragma unroll
        for (int q = 0; q < 4; q++) s[p][q] = 0.f;

    for (int a = 0; a < DIM; a++) {
        float2 qa = *(const float2*)(Qt + a * PQ + i0);
        float4 kb = *(const float4*)(Kt + a * PK + j0);
        s[0][0] = fmaf(qa.x, kb.x, s[0][0]);
        s[0][1] = fmaf(qa.x, kb.y, s[0][1]);
        s[0][2] = fmaf(qa.x, kb.z, s[0][2]);
        s[0][3] = fmaf(qa.x, kb.w, s[0][3]);
        s[1][0] = fmaf(qa.y, kb.x, s[1][0]);
        s[1][1] = fmaf(qa.y, kb.y, s[1][1]);
        s[1][2] = fmaf(qa.y, kb.z, s[1][2]);
        s[1][3] = fmaf(qa.y, kb.w, s[1][3]);
    }
    #pragma unroll
    for (int p = 0; p < 2; p++) {
        int gi = half * 32 + i0 + p;
        #pragma unroll
        for (int q = 0; q < 4; q++) {
            int j = j0 + q;
            float v = (gi >= j) ? s[p][q] * exp2f(LG2G * (float)(gi - j)) : 0.f;
            St[j * PQ + (i0 + p)] = v;
        }
    }
    __syncthreads();

    // overwrite Kt with V in [j][d] layout
    #pragma unroll
    for (int q = 0; q < 16; q++) {
        int f = t + 256 * q;                 // j = f>>6, d = f&63
        Kt[(f >> 6) * PK + (f & 63)] = g_V[base + f];
    }
    __syncthreads();

    // ---- phase 2: out = S V + diag * (Q A)
    const int d0 = tj * 4;
    float o[2][4];
    #pragma unroll
    for (int p = 0; p < 2; p++)
        #pragma unroll
        for (int q = 0; q < 4; q++) o[p][q] = 0.f;

    for (int j = 0; j < CHUNK; j++) {
        float2 sp = *(const float2*)(St + j * PQ + i0);
        float4 vv = *(const float4*)(Kt + j * PK + d0);
        o[0][0] = fmaf(sp.x, vv.x, o[0][0]);
        o[0][1] = fmaf(sp.x, vv.y, o[0][1]);
        o[0][2] = fmaf(sp.x, vv.z, o[0][2]);
        o[0][3] = fmaf(sp.x, vv.w, o[0][3]);
        o[1][0] = fmaf(sp.y, vv.x, o[1][0]);
        o[1][1] = fmaf(sp.y, vv.y, o[1][1]);
        o[1][2] = fmaf(sp.y, vv.z, o[1][2]);
        o[1][3] = fmaf(sp.y, vv.w, o[1][3]);
    }

    const float* A = g_A + (b * NCHUNK + c) * DIM * DIM;
    float oa[2][4];
    #pragma unroll
    for (int p = 0; p < 2; p++)
        #pragma unroll
        for (int q = 0; q < 4; q++) oa[p][q] = 0.f;

    for (int a = 0; a < DIM; a++) {
        float4 av = *(const float4*)(A + a * DIM + d0);
        float2 qa = *(const float2*)(Qt + a * PQ + i0);
        oa[0][0] = fmaf(qa.x, av.x, oa[0][0]);
        oa[0][1] = fmaf(qa.x, av.y, oa[0][1]);
        oa[0][2] = fmaf(qa.x, av.z, oa[0][2]);
        oa[0][3] = fmaf(qa.x, av.w, oa[0][3]);
        oa[1][0] = fmaf(qa.y, av.x, oa[1][0]);
        oa[1][1] = fmaf(qa.y, av.y, oa[1][1]);
        oa[1][2] = fmaf(qa.y, av.z, oa[1][2]);
        oa[1][3] = fmaf(qa.y, av.w, oa[1][3]);
    }

    #pragma unroll
    for (int p = 0; p < 2; p++) {
        int gi = half * 32 + i0 + p;
        float dec = exp2f(LG2G * (float)gi);
        float4 res;
        res.x = o[p][0] + dec * oa[p][0];
        res.y = o[p][1] + dec * oa[p][1];
        res.z = o[p][2] + dec * oa[p][2];
        res.w = o[p][3] + dec * oa[p][3];
        *(float4*)(out + rbase + (i0 + p) * 64 + d0) = res;
    }
}

// ============================== launch ======================================
extern "C" void kernel_launch(void* const* d_in, const int* in_sizes, int n_in,
                              void* d_out, int out_size)
{
    const float* X  = (const float*)d_in[0];
    const float* WQ = (const float*)d_in[1];
    const float* WK = (const float*)d_in[2];
    const float* WV = (const float*)d_in[3];
    float* out = (float*)d_out;

    cudaFuncSetAttribute(gemm_kernel,
                         cudaFuncAttributeMaxDynamicSharedMemorySize, GEMM_SMEM);

    prep_kernel<<<512 + NTOT, 256>>>(WQ, WK, WV);
    gemm_kernel<<<NROWS / 64, 256, GEMM_SMEM>>>(X);
    chunk_kv_kernel<<<BATCH * NCHUNK * 2, 256>>>();
    scan_kernel<<<(BATCH * DIM * DIM) / 128, 128>>>();
    out_kernel<<<BATCH * NCHUNK * 2, 256>>>(out);
}